// round 14
// baseline (speedup 1.0000x reference)
#include <cuda_runtime.h>
#include <cuda_fp16.h>
#include <math.h>
#include <stdint.h>

// Problem dims
#define Bb   8
#define Oo   12
#define Tt   64
#define DMF  256
#define DIF  512
#define DSF  16
#define LL   768          // Oo*Tt
#define MM   6144         // Bb*LL
#define NLAY 2
#define NSEG 6
#define LSEG 128          // LL/NSEG

// ---------------- scratch (static device globals; no runtime allocs) -------
__device__ float  g_x   [MM*DMF];                     // fp32 residual stream
__device__ __align__(16) __half g_xh  [MM*DMF];       // half residual copy
__device__ __align__(16) __half g_xzh [4][(size_t)MM*2*DIF]; // GEMM1 out (half)
__device__ __align__(16) __half g_xch [4][(size_t)MM*DIF];   // conv out (half)
__device__ float  g_dbl [4][(size_t)MM*48];           // GEMM2 out
__device__ __align__(16) __half g_uh  [4][(size_t)MM*DIF];   // scan out (half)
__device__ __align__(8)  __half2 g_dg [4][(size_t)MM*DIF];   // (dv, gate) per step
__device__ float  g_hf  [4*8*NSEG*DIF*16];            // per-segment final h
__device__ float  g_sdv [4*8*NSEG*DIF];               // per-segment sum(dv)
__device__ float  g_o   [2][(size_t)MM*DMF];          // fused GEMM4 out (2 pairs)
// transposed + half weights: [w][n][k]
__device__ __align__(16) __half g_wt1[8*1024*256];
__device__ __align__(16) __half g_wt2[8*64*512];
__device__ __align__(16) __half g_wt4[8*256*512];

__device__ __forceinline__ float siluf(float x){ return x / (1.f + __expf(-x)); }

// ---------------- PTX helpers ----------------------------------------------
__device__ __forceinline__ void mma_f16(float* c, const uint32_t* a, const uint32_t* b){
  asm volatile(
    "mma.sync.aligned.m16n8k16.row.col.f32.f16.f16.f32 "
    "{%0,%1,%2,%3}, {%4,%5,%6,%7}, {%8,%9}, {%0,%1,%2,%3};\n"
    : "+f"(c[0]), "+f"(c[1]), "+f"(c[2]), "+f"(c[3])
    : "r"(a[0]), "r"(a[1]), "r"(a[2]), "r"(a[3]), "r"(b[0]), "r"(b[1]));
}
__device__ __forceinline__ void ldsm4(uint32_t* r, uint32_t addr){
  asm volatile("ldmatrix.sync.aligned.m8n8.x4.shared.b16 {%0,%1,%2,%3}, [%4];"
    : "=r"(r[0]), "=r"(r[1]), "=r"(r[2]), "=r"(r[3]) : "r"(addr));
}
__device__ __forceinline__ void cpa16(uint32_t dst, const void* src){
  asm volatile("cp.async.cg.shared.global [%0], [%1], 16;" :: "r"(dst), "l"(src));
}

// ---------------- weight transpose + fp16 convert ---------------------------
__global__ void wtrans_ker(const float* __restrict__ ip, const float* __restrict__ xp,
                           const float* __restrict__ op){
  int s = blockIdx.z >> 3;
  int w = blockIdx.z & 7;
  int K = (s==0)?256:512;
  int N = (s==0)?1024:((s==1)?48:256);
  int Nout = (s==1)?64:N;
  const float* src = (s==0)?ip:((s==1)?xp:op);
  __half* dst = (s==0)?g_wt1:((s==1)?g_wt2:g_wt4);
  src += (size_t)w*K*N; dst += (size_t)w*(size_t)Nout*K;
  int k0 = blockIdx.x*32, n0 = blockIdx.y*32;
  if (k0 >= K || n0 >= Nout) return;
  __shared__ float tile[32][33];
  int tx = threadIdx.x, ty = threadIdx.y;
  for (int i = ty; i < 32; i += 8){
    int k = k0+i, n = n0+tx;
    tile[i][tx] = (k < K && n < N) ? src[(size_t)k*N + n] : 0.f;
  }
  __syncthreads();
  for (int i = ty; i < 32; i += 8){
    int n = n0+i, k = k0+tx;
    if (n < Nout && k < K) dst[(size_t)n*K + k] = __float2half(tile[tx][i]);
  }
}

// ---------------- elementwise kernels --------------------------------------
__global__ void add_pe_ker(const float* __restrict__ x, const float* __restrict__ pe){
  int i = blockIdx.x, c = threadIdx.x;
  int t = i % Tt;
  float v = x[(size_t)i*DMF + c] + pe[t*DMF + c];
  g_x [(size_t)i*DMF + c] = v;
  g_xh[(size_t)i*DMF + c] = __float2half(v);
}

// ---------------- fp16 tensor-core GEMM (ldmatrix + cp.async) --------------
#define STRH 40
#define ABUF (128*STRH)
template<int NT>
__global__ void __launch_bounds__(256) hgemm_ker(
    const __half* __restrict__ A0, size_t zstr,
    const __half* __restrict__ WtB, void* __restrict__ Cb,
    int K, int Ntot, int l, int perm, int hout)
{
  constexpr int BBUF = NT*STRH;
  extern __shared__ __half smh[];
  const uint32_t sb = (uint32_t)__cvta_generic_to_shared(smh);
  const uint32_t aOff[2] = {0u, (uint32_t)ABUF*2u};
  const uint32_t bOff[2] = {(uint32_t)(2*ABUF)*2u, (uint32_t)(2*ABUF + BBUF)*2u};

  const int z = blockIdx.z;
  const __half* A = A0 + (size_t)z*zstr;
  const int n0 = blockIdx.y * NT;
  const int Nrows = (Ntot==48) ? 64 : Ntot;
  const __half* Wt = WtB + ((size_t)(l*4 + z)*Nrows + n0) * K;

  const int tid  = threadIdx.x;
  const int lane = tid & 31;
  const int w    = tid >> 5;
  constexpr int WN = NT/4;
  constexpr int NATOMS = WN/8;
  constexpr int NPAIRS = WN/16;
  const int wm = (w & 1) * 64;
  const int wn = (w >> 1) * WN;
  const int row0 = blockIdx.x * 128;

  float acc[4][NATOMS][4];
  #pragma unroll
  for (int ma = 0; ma < 4; ma++)
    #pragma unroll
    for (int na = 0; na < NATOMS; na++)
      #pragma unroll
      for (int q = 0; q < 4; q++) acc[ma][na][q] = 0.f;

  const int a_r = tid >> 1;
  const int a_u = (tid & 1) * 2;
  int grow = row0 + a_r;
  if (perm && z >= 2){
    int b2 = grow / LL;
    int p  = grow - b2*LL;
    int tq = p / Oo;
    int o  = p - tq*Oo;
    grow = b2*LL + o*Tt + tq;
  }
  const __half* Arow = A + (size_t)grow*K;

  const uint32_t aLd = (uint32_t)((wm + (lane & 15))*STRH + (lane >> 4)*8) * 2u;
  const int nloc = ((lane & 16) >> 1) | (lane & 7);
  const uint32_t bLd = (uint32_t)((wn + nloc)*STRH + ((lane >> 3) & 1)*8) * 2u;

  auto load_chunk = [&](int buf, int c){
    const int kb = c*32;
    const uint32_t ab = sb + aOff[buf];
    const uint32_t bb = sb + bOff[buf];
    #pragma unroll
    for (int u = 0; u < 2; u++)
      cpa16(ab + (uint32_t)(a_r*STRH + (a_u+u)*8)*2u, Arow + kb + (a_u+u)*8);
    #pragma unroll
    for (int it = 0; it < NT/64; it++){
      int idx = tid + it*256;
      int r = idx >> 2, u = idx & 3;
      cpa16(bb + (uint32_t)(r*STRH + u*8)*2u, &Wt[(size_t)r*K + kb + u*8]);
    }
    asm volatile("cp.async.commit_group;" ::: "memory");
  };

  auto compute = [&](int buf){
    const uint32_t ab = sb + aOff[buf];
    const uint32_t bb = sb + bOff[buf];
    #pragma unroll
    for (int ks = 0; ks < 2; ks++){
      uint32_t af[4][4];
      #pragma unroll
      for (int ma = 0; ma < 4; ma++)
        ldsm4(af[ma], ab + aLd + (uint32_t)(ma*16*STRH + ks*16)*2u);
      uint32_t bf[2*NPAIRS][2];
      #pragma unroll
      for (int np = 0; np < NPAIRS; np++){
        uint32_t r4[4];
        ldsm4(r4, bb + bLd + (uint32_t)(np*16*STRH + ks*16)*2u);
        bf[np*2+0][0] = r4[0]; bf[np*2+0][1] = r4[1];
        bf[np*2+1][0] = r4[2]; bf[np*2+1][1] = r4[3];
      }
      #pragma unroll
      for (int ma = 0; ma < 4; ma++)
        #pragma unroll
        for (int na = 0; na < NATOMS; na++)
          mma_f16(acc[ma][na], af[ma], bf[na]);
    }
  };

  const int nc = K / 32;
  load_chunk(0, 0);
  for (int c = 0; c < nc; c++){
    const int buf = c & 1;
    if (c + 1 < nc){
      load_chunk(buf ^ 1, c + 1);
      asm volatile("cp.async.wait_group 1;" ::: "memory");
    } else {
      asm volatile("cp.async.wait_group 0;" ::: "memory");
    }
    __syncthreads();
    compute(buf);
    __syncthreads();
  }

  if (hout){
    __half* Ch = (__half*)Cb + (size_t)z * (size_t)MM * Ntot;
    #pragma unroll
    for (int ma = 0; ma < 4; ma++){
      const int r = row0 + wm + ma*16 + (lane >> 2);
      #pragma unroll
      for (int na = 0; na < NATOMS; na++){
        const int cc = n0 + wn + na*8 + (lane & 3)*2;
        if (cc < Ntot){
          *reinterpret_cast<__half2*>(&Ch[(size_t)r*Ntot + cc])     = __floats2half2_rn(acc[ma][na][0], acc[ma][na][1]);
          *reinterpret_cast<__half2*>(&Ch[(size_t)(r+8)*Ntot + cc]) = __floats2half2_rn(acc[ma][na][2], acc[ma][na][3]);
        }
      }
    }
  } else {
    float* C = (float*)Cb + (size_t)z * (size_t)MM * Ntot;
    #pragma unroll
    for (int ma = 0; ma < 4; ma++){
      const int r = row0 + wm + ma*16 + (lane >> 2);
      #pragma unroll
      for (int na = 0; na < NATOMS; na++){
        const int cc = n0 + wn + na*8 + (lane & 3)*2;
        if (cc < Ntot){
          *reinterpret_cast<float2*>(&C[(size_t)r*Ntot + cc])     = make_float2(acc[ma][na][0], acc[ma][na][1]);
          *reinterpret_cast<float2*>(&C[(size_t)(r+8)*Ntot + cc]) = make_float2(acc[ma][na][2], acc[ma][na][3]);
        }
      }
    }
  }
}

// ---------------- fused out-proj pair GEMM: o[p] = [u(2p),u(2p+1)] @ [W;W] --
__global__ void __launch_bounds__(256) hgemm_pair_ker(int l){
  constexpr int NT = 128;
  constexpr int BBUF = NT*STRH;
  extern __shared__ __half smh[];
  const uint32_t sb = (uint32_t)__cvta_generic_to_shared(smh);
  const uint32_t aOff[2] = {0u, (uint32_t)ABUF*2u};
  const uint32_t bOff[2] = {(uint32_t)(2*ABUF)*2u, (uint32_t)(2*ABUF + BBUF)*2u};

  const int p = blockIdx.z;
  const int n0 = blockIdx.y * NT;
  const int tid  = threadIdx.x;
  const int lane = tid & 31;
  const int w    = tid >> 5;
  const int wm = (w & 1) * 64;
  const int wn = (w >> 1) * 32;
  const int row0 = blockIdx.x * 128;

  const __half* Alo = g_uh[p*2];
  const __half* Ahi = g_uh[p*2+1];
  const __half* Wlo = g_wt4 + (size_t)(l*4 + p*2    )*256*512;
  const __half* Whi = g_wt4 + (size_t)(l*4 + p*2 + 1)*256*512;

  float acc[4][4][4];
  #pragma unroll
  for (int ma = 0; ma < 4; ma++)
    #pragma unroll
    for (int na = 0; na < 4; na++)
      #pragma unroll
      for (int q = 0; q < 4; q++) acc[ma][na][q] = 0.f;

  const int a_r = tid >> 1;
  const int a_u = (tid & 1) * 2;
  const int grow = row0 + a_r;

  const uint32_t aLd = (uint32_t)((wm + (lane & 15))*STRH + (lane >> 4)*8) * 2u;
  const int nloc = ((lane & 16) >> 1) | (lane & 7);
  const uint32_t bLd = (uint32_t)((wn + nloc)*STRH + ((lane >> 3) & 1)*8) * 2u;

  auto load_chunk = [&](int buf, int c){
    const int kb = c*32;
    const bool hi = (kb >= 512);
    const int kk = hi ? (kb - 512) : kb;
    const __half* Asrc = (hi ? Ahi : Alo) + (size_t)grow*DIF + kk;
    const __half* Wsrc = (hi ? Whi : Wlo);
    const uint32_t ab = sb + aOff[buf];
    const uint32_t bb = sb + bOff[buf];
    #pragma unroll
    for (int u = 0; u < 2; u++)
      cpa16(ab + (uint32_t)(a_r*STRH + (a_u+u)*8)*2u, Asrc + (a_u+u)*8);
    #pragma unroll
    for (int it = 0; it < 2; it++){
      int idx = tid + it*256;
      int r = idx >> 2, u = idx & 3;
      cpa16(bb + (uint32_t)(r*STRH + u*8)*2u,
            &Wsrc[(size_t)(n0 + r)*512 + kk + u*8]);
    }
    asm volatile("cp.async.commit_group;" ::: "memory");
  };

  auto compute = [&](int buf){
    const uint32_t ab = sb + aOff[buf];
    const uint32_t bb = sb + bOff[buf];
    #pragma unroll
    for (int ks = 0; ks < 2; ks++){
      uint32_t af[4][4];
      #pragma unroll
      for (int ma = 0; ma < 4; ma++)
        ldsm4(af[ma], ab + aLd + (uint32_t)(ma*16*STRH + ks*16)*2u);
      uint32_t bf[4][2];
      #pragma unroll
      for (int np = 0; np < 2; np++){
        uint32_t r4[4];
        ldsm4(r4, bb + bLd + (uint32_t)(np*16*STRH + ks*16)*2u);
        bf[np*2+0][0] = r4[0]; bf[np*2+0][1] = r4[1];
        bf[np*2+1][0] = r4[2]; bf[np*2+1][1] = r4[3];
      }
      #pragma unroll
      for (int ma = 0; ma < 4; ma++)
        #pragma unroll
        for (int na = 0; na < 4; na++)
          mma_f16(acc[ma][na], af[ma], bf[na]);
    }
  };

  const int nc = 1024 / 32;
  load_chunk(0, 0);
  for (int c = 0; c < nc; c++){
    const int buf = c & 1;
    if (c + 1 < nc){
      load_chunk(buf ^ 1, c + 1);
      asm volatile("cp.async.wait_group 1;" ::: "memory");
    } else {
      asm volatile("cp.async.wait_group 0;" ::: "memory");
    }
    __syncthreads();
    compute(buf);
    __syncthreads();
  }

  float* C = g_o[p];
  #pragma unroll
  for (int ma = 0; ma < 4; ma++){
    const int r = row0 + wm + ma*16 + (lane >> 2);
    #pragma unroll
    for (int na = 0; na < 4; na++){
      const int cc = n0 + wn + na*8 + (lane & 3)*2;
      *reinterpret_cast<float2*>(&C[(size_t)r*DMF + cc])     = make_float2(acc[ma][na][0], acc[ma][na][1]);
      *reinterpret_cast<float2*>(&C[(size_t)(r+8)*DMF + cc]) = make_float2(acc[ma][na][2], acc[ma][na][3]);
    }
  }
}

// ---------------- depthwise causal conv + SiLU (half in/out, 4 t/thread) ---
__global__ void conv_ker(const float* __restrict__ conv_w, const float* __restrict__ conv_b, int l){
  int z   = blockIdx.y;
  int gid = blockIdx.x*256 + threadIdx.x;
  const int NT4 = LL/4;
  int i4 = gid / (DIF/4);
  int dq = gid % (DIF/4);
  int d  = dq*4;
  int b  = i4 / NT4;
  int t0 = (i4 - b*NT4)*4;
  int widx = l*4 + z;
  const __half* xz = g_xzh[z];

  float wv[4][4], bi[4];
  #pragma unroll
  for (int di = 0; di < 4; di++){
    float4 w4 = *reinterpret_cast<const float4*>(&conv_w[(size_t)(widx*DIF + d+di)*4]);
    wv[di][0]=w4.x; wv[di][1]=w4.y; wv[di][2]=w4.z; wv[di][3]=w4.w;
  }
  {
    float4 b4 = *reinterpret_cast<const float4*>(&conv_b[(size_t)widx*DIF + d]);
    bi[0]=b4.x; bi[1]=b4.y; bi[2]=b4.z; bi[3]=b4.w;
  }
  size_t base = (size_t)b*LL;
  float v[7][4];
  bool fwd = ((z & 1) == 0);
  #pragma unroll
  for (int j = 0; j < 7; j++){
    int tt = fwd ? (t0 + j - 3) : (t0 + j);
    if (tt >= 0 && tt < LL){
      const __half2* p2 = reinterpret_cast<const __half2*>(&xz[(base+tt)*1024 + d]);
      float2 a = __half22float2(p2[0]), c2 = __half22float2(p2[1]);
      v[j][0]=a.x; v[j][1]=a.y; v[j][2]=c2.x; v[j][3]=c2.y;
    } else {
      v[j][0]=v[j][1]=v[j][2]=v[j][3]=0.f;
    }
  }
  #pragma unroll
  for (int k = 0; k < 4; k++){
    float o[4];
    #pragma unroll
    for (int di = 0; di < 4; di++){
      float s = bi[di];
      if (fwd){
        #pragma unroll
        for (int i2 = 0; i2 < 4; i2++) s = fmaf(wv[di][i2], v[k+i2][di], s);
      } else {
        #pragma unroll
        for (int j = 0; j < 4; j++)    s = fmaf(wv[di][3-j], v[k+j][di], s);
      }
      o[di] = siluf(s);
    }
    __half2* oh = reinterpret_cast<__half2*>(&g_xch[z][(base + t0 + k)*DIF + d]);
    oh[0] = __floats2half2_rn(o[0], o[1]);
    oh[1] = __floats2half2_rn(o[2], o[3]);
  }
}

// ---------------- scan phase 1: per-segment local scan (h0 = 0) ------------
#define S1CH 16
#define oDBL 0
#define oXC  6144
#define oZ   14336
#define S1_SMEM 22528
__global__ void __launch_bounds__(128, 6) scan1_ker(const float* __restrict__ A_log,
                                                 const float* __restrict__ Dp,
                                                 const float* __restrict__ dtw,
                                                 const float* __restrict__ dtb, int l){
  extern __shared__ char ssm[];
  const uint32_t sb = (uint32_t)__cvta_generic_to_shared(ssm);
  int tid = threadIdx.x;
  int d0 = blockIdx.x*128, d = d0 + tid;
  int b = blockIdx.y;
  int z = blockIdx.z / NSEG, seg = blockIdx.z - z*NSEG;
  int widx = l*4 + z;
  bool bwd = (z & 1);
  const __half* xch = g_xch[z];
  const __half* xzz = g_xzh[z];
  const float*  dbl = g_dbl[z];
  __half*  u  = g_uh[z];
  __half2* dg = g_dg[z];

  float W[16];
  #pragma unroll
  for (int k = 0; k < 16; k++) W[k] = dtw[((size_t)widx*16 + k)*DIF + d];
  float bia = dtb[(size_t)widx*DIF + d];
  float Av[16];
  #pragma unroll
  for (int s = 0; s < 16; s++)
    Av[s] = -expf(A_log[((size_t)widx*DIF + d)*DSF + s]);
  bool pc = true;
  #pragma unroll
  for (int s = 1; s < 16; s++)
    pc = pc && (fabsf(Av[s] - (float)(s+1)*Av[0]) <= 1e-4f * fabsf(Av[s]));
  float Dpar = Dp[(size_t)widx*DIF + d];

  float h[16];
  #pragma unroll
  for (int s = 0; s < 16; s++) h[s] = 0.f;
  float sumdv = 0.f;
  const int gi0 = seg*LSEG;

  auto load_chunk = [&](int c, int buf){
    #pragma unroll
    for (int it = 0; it < 2; it++){
      int idx = tid + it*128;
      if (idx < S1CH*12){
        int ls = idx / 12, q = idx - ls*12;
        int gi = gi0 + c*S1CH + ls;
        int t = bwd ? (LL-1 - gi) : gi;
        cpa16(sb + oDBL + (uint32_t)(((buf*S1CH + ls)*12 + q)*16),
              &dbl[(size_t)(b*LL + t)*48 + q*4]);
      }
    }
    #pragma unroll
    for (int it = 0; it < 2; it++){
      int idx = tid + it*128;
      int ls = idx >> 4, sg = idx & 15;
      int gi = gi0 + c*S1CH + ls;
      int t = bwd ? (LL-1 - gi) : gi;
      cpa16(sb + oXC + (uint32_t)(((buf*S1CH + ls)*128 + sg*8)*2),
            &xch[(size_t)(b*LL + t)*DIF + d0 + sg*8]);
      cpa16(sb + oZ + (uint32_t)(((buf*S1CH + ls)*128 + sg*8)*2),
            &xzz[(size_t)(b*LL + t)*1024 + DIF + d0 + sg*8]);
    }
    asm volatile("cp.async.commit_group;" ::: "memory");
  };

  const int nc = LSEG / S1CH;   // 8
  load_chunk(0, 0);
  for (int c = 0; c < nc; c++){
    const int buf = c & 1;
    if (c + 1 < nc){
      load_chunk(c + 1, buf ^ 1);
      asm volatile("cp.async.wait_group 1;" ::: "memory");
    } else {
      asm volatile("cp.async.wait_group 0;" ::: "memory");
    }
    __syncthreads();
    const float4* sD = reinterpret_cast<const float4*>(ssm + oDBL) + (size_t)buf*S1CH*12;
    const __half* sX = reinterpret_cast<const __half*>(ssm + oXC) + (size_t)buf*S1CH*128;
    const __half* sZ = reinterpret_cast<const __half*>(ssm + oZ)  + (size_t)buf*S1CH*128;

    for (int ls = 0; ls < S1CH; ls++){
      int gi = gi0 + c*S1CH + ls;
      int t  = bwd ? (LL-1 - gi) : gi;
      float xcv = __half2float(sX[ls*128 + tid]);
      float zv  = __half2float(sZ[ls*128 + tid]);
      const float4* row = sD + ls*12;
      float4 q0 = row[0], q1 = row[1], q2 = row[2], q3 = row[3];
      float a0 = fmaf(q0.x, W[0],  fmaf(q0.y, W[1],  fmaf(q0.z, W[2],  q0.w*W[3])));
      float a1 = fmaf(q1.x, W[4],  fmaf(q1.y, W[5],  fmaf(q1.z, W[6],  q1.w*W[7])));
      float a2 = fmaf(q2.x, W[8],  fmaf(q2.y, W[9],  fmaf(q2.z, W[10], q2.w*W[11])));
      float a3 = fmaf(q3.x, W[12], fmaf(q3.y, W[13], fmaf(q3.z, W[14], q3.w*W[15])));
      float a = bia + ((a0 + a1) + (a2 + a3));
      float dv = fmaxf(a, 0.f) + log1pf(__expf(-fabsf(a)));
      sumdv += dv;
      float du = dv * xcv;

      float acc0 = 0.f, acc1 = 0.f, acc2 = 0.f, acc3 = 0.f;
      if (pc){
        float e1 = __expf(dv * Av[0]);
        float e2 = e1*e1, e3 = e2*e1, e4 = e2*e2;
        float e5 = e4*e1, e6 = e4*e2, e7 = e4*e3, e8 = e4*e4;
        float e9 = e8*e1, e10 = e8*e2, e11 = e8*e3, e12 = e8*e4;
        float e13 = e8*e5, e14 = e8*e6, e15 = e8*e7, e16 = e8*e8;
        float4 B0 = row[4], B1 = row[5], B2 = row[6], B3 = row[7];
        float4 C0 = row[8], C1 = row[9], C2 = row[10], C3 = row[11];
        h[0]  = fmaf(e1,  h[0],  du*B0.x); acc0 = fmaf(h[0],  C0.x, acc0);
        h[1]  = fmaf(e2,  h[1],  du*B0.y); acc1 = fmaf(h[1],  C0.y, acc1);
        h[2]  = fmaf(e3,  h[2],  du*B0.z); acc2 = fmaf(h[2],  C0.z, acc2);
        h[3]  = fmaf(e4,  h[3],  du*B0.w); acc3 = fmaf(h[3],  C0.w, acc3);
        h[4]  = fmaf(e5,  h[4],  du*B1.x); acc0 = fmaf(h[4],  C1.x, acc0);
        h[5]  = fmaf(e6,  h[5],  du*B1.y); acc1 = fmaf(h[5],  C1.y, acc1);
        h[6]  = fmaf(e7,  h[6],  du*B1.z); acc2 = fmaf(h[6],  C1.z, acc2);
        h[7]  = fmaf(e8,  h[7],  du*B1.w); acc3 = fmaf(h[7],  C1.w, acc3);
        h[8]  = fmaf(e9,  h[8],  du*B2.x); acc0 = fmaf(h[8],  C2.x, acc0);
        h[9]  = fmaf(e10, h[9],  du*B2.y); acc1 = fmaf(h[9],  C2.y, acc1);
        h[10] = fmaf(e11, h[10], du*B2.z); acc2 = fmaf(h[10], C2.z, acc2);
        h[11] = fmaf(e12, h[11], du*B2.w); acc3 = fmaf(h[11], C2.w, acc3);
        h[12] = fmaf(e13, h[12], du*B3.x); acc0 = fmaf(h[12], C3.x, acc0);
        h[13] = fmaf(e14, h[13], du*B3.y); acc1 = fmaf(h[13], C3.y, acc1);
        h[14] = fmaf(e15, h[14], du*B3.z); acc2 = fmaf(h[14], C3.z, acc2);
        h[15] = fmaf(e16, h[15], du*B3.w); acc3 = fmaf(h[15], C3.w, acc3);
      } else {
        #pragma unroll
        for (int q = 0; q < 4; q++){
          float4 B4 = row[4+q];
          float4 C4 = row[8+q];
          float b0 = __expf(dv*Av[q*4+0]); h[q*4+0] = fmaf(b0, h[q*4+0], du*B4.x); acc0 = fmaf(h[q*4+0], C4.x, acc0);
          float b1 = __expf(dv*Av[q*4+1]); h[q*4+1] = fmaf(b1, h[q*4+1], du*B4.y); acc1 = fmaf(h[q*4+1], C4.y, acc1);
          float b2 = __expf(dv*Av[q*4+2]); h[q*4+2] = fmaf(b2, h[q*4+2], du*B4.z); acc2 = fmaf(h[q*4+2], C4.z, acc2);
          float b3 = __expf(dv*Av[q*4+3]); h[q*4+3] = fmaf(b3, h[q*4+3], du*B4.w); acc3 = fmaf(h[q*4+3], C4.w, acc3);
        }
      }
      float gate = siluf(zv);
      float y = (acc0 + acc1) + (acc2 + acc3) + xcv * Dpar;
      size_t rowd = (size_t)(b*LL + t)*DIF + d;
      u[rowd]  = __float2half(y * gate);
      dg[rowd] = __floats2half2_rn(dv, gate);
    }
    __syncthreads();
  }
  int segbase = ((z*8 + b)*NSEG + seg)*DIF + d;
  float4* hf4 = reinterpret_cast<float4*>(&g_hf[(size_t)segbase*16]);
  hf4[0] = make_float4(h[0],  h[1],  h[2],  h[3]);
  hf4[1] = make_float4(h[4],  h[5],  h[6],  h[7]);
  hf4[2] = make_float4(h[8],  h[9],  h[10], h[11]);
  hf4[3] = make_float4(h[12], h[13], h[14], h[15]);
  g_sdv[segbase] = sumdv;
}

// ---------------- scan phase 2: cross-segment correction (early exit) ------
#define S2CH 16
#define oC2  0
#define oDG2 2048
#define oU2  18432
#define S2_SMEM 26624
__global__ void __launch_bounds__(128, 6) scan2_ker(const float* __restrict__ A_log, int l){
  extern __shared__ char ssm[];
  const uint32_t sb = (uint32_t)__cvta_generic_to_shared(ssm);
  int tid = threadIdx.x;
  int d0 = blockIdx.x*128, d = d0 + tid;
  int b = blockIdx.y;
  int z = blockIdx.z / (NSEG-1), seg = blockIdx.z - z*(NSEG-1) + 1;
  int widx = l*4 + z;
  bool bwd = (z & 1);
  const float*  dbl = g_dbl[z];
  const __half2* dg = g_dg[z];
  __half* u = g_uh[z];

  float Av[16];
  #pragma unroll
  for (int s = 0; s < 16; s++)
    Av[s] = -expf(A_log[((size_t)widx*DIF + d)*DSF + s]);
  bool pc = true;
  #pragma unroll
  for (int s = 1; s < 16; s++)
    pc = pc && (fabsf(Av[s] - (float)(s+1)*Av[0]) <= 1e-4f * fabsf(Av[s]));
  float amax = Av[0];
  #pragma unroll
  for (int s = 1; s < 16; s++) amax = fmaxf(amax, Av[s]);

  float hin[16];
  #pragma unroll
  for (int s = 0; s < 16; s++) hin[s] = 0.f;
  for (int k = 0; k < seg; k++){
    int kb = ((z*8 + b)*NSEG + k)*DIF + d;
    float sd = g_sdv[kb];
    const float4* hf4 = reinterpret_cast<const float4*>(&g_hf[(size_t)kb*16]);
    float4 f0 = hf4[0], f1 = hf4[1], f2 = hf4[2], f3 = hf4[3];
    float hf[16] = {f0.x,f0.y,f0.z,f0.w, f1.x,f1.y,f1.z,f1.w,
                    f2.x,f2.y,f2.z,f2.w, f3.x,f3.y,f3.z,f3.w};
    if (pc){
      float E = __expf(Av[0]*sd);
      float p = 1.f;
      #pragma unroll
      for (int s = 0; s < 16; s++){ p *= E; hin[s] = fmaf(p, hin[s], hf[s]); }
    } else {
      #pragma unroll
      for (int s = 0; s < 16; s++) hin[s] = fmaf(__expf(Av[s]*sd), hin[s], hf[s]);
    }
  }

  const int gi0 = seg*LSEG;
  auto load_chunk = [&](int c, int buf){
    if (tid < S2CH*4){
      int ls = tid >> 2, q = tid & 3;
      int gi = gi0 + c*S2CH + ls;
      int t = bwd ? (LL-1 - gi) : gi;
      cpa16(sb + oC2 + (uint32_t)(((buf*S2CH + ls)*4 + q)*16),
            &dbl[(size_t)(b*LL + t)*48 + 32 + q*4]);
    }
    #pragma unroll
    for (int it = 0; it < 4; it++){
      int idx = tid + it*128;
      int ls = idx >> 5, sg = idx & 31;
      int gi = gi0 + c*S2CH + ls;
      int t = bwd ? (LL-1 - gi) : gi;
      cpa16(sb + oDG2 + (uint32_t)(((buf*S2CH + ls)*128 + sg*4)*4),
            &dg[(size_t)(b*LL + t)*DIF + d0 + sg*4]);
    }
    #pragma unroll
    for (int it = 0; it < 2; it++){
      int idx = tid + it*128;
      int ls = idx >> 4, sg = idx & 15;
      int gi = gi0 + c*S2CH + ls;
      int t = bwd ? (LL-1 - gi) : gi;
      cpa16(sb + oU2 + (uint32_t)(((buf*S2CH + ls)*128 + sg*8)*2),
            &u[(size_t)(b*LL + t)*DIF + d0 + sg*8]);
    }
    asm volatile("cp.async.commit_group;" ::: "memory");
  };

  float cacc = 0.f;
  const int nc = LSEG / S2CH;   // 8
  load_chunk(0, 0);
  for (int c = 0; c < nc; c++){
    const int buf = c & 1;
    if (c + 1 < nc){
      load_chunk(c + 1, buf ^ 1);
      asm volatile("cp.async.wait_group 1;" ::: "memory");
    } else {
      asm volatile("cp.async.wait_group 0;" ::: "memory");
    }
    __syncthreads();
    const float4*  sC = reinterpret_cast<const float4*>(ssm + oC2) + (size_t)buf*S2CH*4;
    const __half2* sG = reinterpret_cast<const __half2*>(ssm + oDG2) + (size_t)buf*S2CH*128;
    const __half*  sU = reinterpret_cast<const __half*>(ssm + oU2) + (size_t)buf*S2CH*128;

    for (int ls = 0; ls < S2CH; ls++){
      int gi = gi0 + c*S2CH + ls;
      int t  = bwd ? (LL-1 - gi) : gi;
      float2 dgv = __half22float2(sG[ls*128 + tid]);
      cacc += dgv.x;
      float4 C0 = sC[ls*4+0], C1 = sC[ls*4+1], C2 = sC[ls*4+2], C3 = sC[ls*4+3];
      float corr;
      if (pc){
        float e1 = __expf(Av[0]*cacc);
        float e2 = e1*e1, e3 = e2*e1, e4 = e2*e2;
        float e5 = e4*e1, e6 = e4*e2, e7 = e4*e3, e8 = e4*e4;
        float e9 = e8*e1, e10 = e8*e2, e11 = e8*e3, e12 = e8*e4;
        float e13 = e8*e5, e14 = e8*e6, e15 = e8*e7, e16 = e8*e8;
        float c0 = fmaf(e1*hin[0],  C0.x, 0.f);
        c0 = fmaf(e5*hin[4],  C1.x, c0);
        c0 = fmaf(e9*hin[8],  C2.x, c0);
        c0 = fmaf(e13*hin[12], C3.x, c0);
        float c1 = fmaf(e2*hin[1],  C0.y, 0.f);
        c1 = fmaf(e6*hin[5],  C1.y, c1);
        c1 = fmaf(e10*hin[9], C2.y, c1);
        c1 = fmaf(e14*hin[13], C3.y, c1);
        float c2 = fmaf(e3*hin[2],  C0.z, 0.f);
        c2 = fmaf(e7*hin[6],  C1.z, c2);
        c2 = fmaf(e11*hin[10], C2.z, c2);
        c2 = fmaf(e15*hin[14], C3.z, c2);
        float c3 = fmaf(e4*hin[3],  C0.w, 0.f);
        c3 = fmaf(e8*hin[7],  C1.w, c3);
        c3 = fmaf(e12*hin[11], C2.w, c3);
        c3 = fmaf(e16*hin[15], C3.w, c3);
        corr = (c0 + c1) + (c2 + c3);
      } else {
        float Cw[16] = {C0.x,C0.y,C0.z,C0.w, C1.x,C1.y,C1.z,C1.w,
                        C2.x,C2.y,C2.z,C2.w, C3.x,C3.y,C3.z,C3.w};
        corr = 0.f;
        #pragma unroll
        for (int s = 0; s < 16; s++)
          corr = fmaf(__expf(Av[s]*cacc)*hin[s], Cw[s], corr);
      }
      float up = __half2float(sU[ls*128 + tid]);
      u[(size_t)(b*LL + t)*DIF + d] = __float2half(fmaf(corr, dgv.y, up));
    }
    int done = (cacc * (-amax) > 25.f) ? 1 : 0;
    if (__syncthreads_and(done)){
      asm volatile("cp.async.wait_group 0;" ::: "memory");
      break;
    }
  }
}

// ---------------- combine: LN(o0), LN(o1), residual add; optional out ------
__global__ void combine_ker(const float* __restrict__ lnw, const float* __restrict__ lnb,
                            float* __restrict__ out, int last){
  int i = blockIdx.x, c = threadIdx.x;
  float a  = g_o[0][(size_t)i*DMF + c];
  float bv = g_o[1][(size_t)i*DMF + c];
  __shared__ float r1[256], r2[256];
  r1[c] = a; r2[c] = bv; __syncthreads();
  for (int s = 128; s > 0; s >>= 1){
    if (c < s){ r1[c] += r1[c+s]; r2[c] += r2[c+s]; }
    __syncthreads();
  }
  float ma = r1[0] * (1.f/DMF), mb = r2[0] * (1.f/DMF);
  __syncthreads();
  float da = a - ma, db = bv - mb;
  r1[c] = da*da; r2[c] = db*db; __syncthreads();
  for (int s = 128; s > 0; s >>= 1){
    if (c < s){ r1[c] += r1[c+s]; r2[c] += r2[c+s]; }
    __syncthreads();
  }
  float va = r1[0] * (1.f/DMF), vb = r2[0] * (1.f/DMF);
  float s1 = da * rsqrtf(va + 1e-5f) * lnw[c] + lnb[c];
  float s2 = db * rsqrtf(vb + 1e-5f) * lnw[c] + lnb[c];
  float nv = g_x[(size_t)i*DMF + c] + 0.5f * (s1 + s2);
  g_x [(size_t)i*DMF + c] = nv;
  g_xh[(size_t)i*DMF + c] = __float2half(nv);
  if (last) out[(size_t)i*DMF + c] = nv;
}

// ---------------- host orchestration ---------------------------------------
#define SMEM_H128 ((2*ABUF + 2*128*STRH)*2)   // 40960 B
#define SMEM_H64  ((2*ABUF + 2*64*STRH)*2)    // 30720 B

extern "C" void kernel_launch(void* const* d_in, const int* in_sizes, int n_in,
                              void* d_out, int out_size){
  const float* x       = (const float*)d_in[0];
  const float* pe      = (const float*)d_in[1];
  const float* ln_w    = (const float*)d_in[2];
  const float* ln_b    = (const float*)d_in[3];
  const float* in_proj = (const float*)d_in[4];
  const float* conv_w  = (const float*)d_in[5];
  const float* conv_b  = (const float*)d_in[6];
  const float* x_proj  = (const float*)d_in[7];
  const float* dt_w    = (const float*)d_in[8];
  const float* dt_b    = (const float*)d_in[9];
  const float* A_log   = (const float*)d_in[10];
  const float* Dp      = (const float*)d_in[11];
  const float* out_prj = (const float*)d_in[12];

  void *pxh, *pxzh, *pxch, *pdbl, *pw1, *pw2;
  cudaGetSymbolAddress(&pxh,  g_xh);
  cudaGetSymbolAddress(&pxzh, g_xzh);
  cudaGetSymbolAddress(&pxch, g_xch);
  cudaGetSymbolAddress(&pdbl, g_dbl);
  cudaGetSymbolAddress(&pw1,  g_wt1);
  cudaGetSymbolAddress(&pw2,  g_wt2);

  cudaFuncSetAttribute(scan1_ker, cudaFuncAttributeMaxDynamicSharedMemorySize, S1_SMEM);
  cudaFuncSetAttribute(scan2_ker, cudaFuncAttributeMaxDynamicSharedMemorySize, S2_SMEM);

  wtrans_ker<<<dim3(16, 32, 24), dim3(32, 8)>>>(in_proj, x_proj, out_prj);
  add_pe_ker<<<MM, 256>>>(x, pe);

  for (int l = 0; l < NLAY; l++){
    // GEMM1: xz[z] = seq(z) @ in_proj[l,z]  (N=1024, K=256, half out)
    hgemm_ker<128><<<dim3(MM/128, 8, 4), 256, SMEM_H128>>>(
        (const __half*)pxh, (size_t)0,
        (const __half*)pw1, pxzh, 256, 1024, l, 1, 1);
    conv_ker<<<dim3((MM/4)*(DIF/4)/256, 4), 256>>>(conv_w, conv_b, l);
    // GEMM2: dbl[z] = xc[z] @ x_proj (N=48 pad 64, K=512, fp32 out)
    hgemm_ker<64><<<dim3(MM/128, 1, 4), 256, SMEM_H64>>>(
        (const __half*)pxch, (size_t)MM*DIF,
        (const __half*)pw2, pdbl, 512, 48, l, 0, 0);
    // selective scan: 6-segment phase 1 + early-exit fixup
    scan1_ker<<<dim3(4, Bb, 4*NSEG), 128, S1_SMEM>>>(A_log, Dp, dt_w, dt_b, l);
    scan2_ker<<<dim3(4, Bb, 4*(NSEG-1)), 128, S2_SMEM>>>(A_log, l);
    // GEMM4 fused pairs: o[p] = [u(2p) u(2p+1)] @ stacked Wt (K=1024)
    hgemm_pair_ker<<<dim3(MM/128, 2, 2), 256, SMEM_H128>>>(l);
    combine_ker<<<MM, 256>>>(ln_w, ln_b, (float*)d_out, (l == NLAY-1) ? 1 : 0);
  }
}

// round 15
// speedup vs baseline: 1.0186x; 1.0186x over previous
#include <cuda_runtime.h>
#include <cuda_fp16.h>
#include <math.h>
#include <stdint.h>

// Problem dims
#define Bb   8
#define Oo   12
#define Tt   64
#define DMF  256
#define DIF  512
#define DSF  16
#define LL   768          // Oo*Tt
#define MM   6144         // Bb*LL
#define NLAY 2
#define NSEG 8
#define LSEG 96           // LL/NSEG

// ---------------- scratch (static device globals; no runtime allocs) -------
__device__ float  g_x   [MM*DMF];                     // fp32 residual stream
__device__ __align__(16) __half g_xh  [MM*DMF];       // half residual copy
__device__ __align__(16) __half g_xzh [4][(size_t)MM*2*DIF]; // GEMM1 out (half)
__device__ __align__(16) __half g_xch [4][(size_t)MM*DIF];   // conv out (half)
__device__ float  g_dbl [4][(size_t)MM*48];           // GEMM2 out
__device__ __align__(16) __half g_uh  [4][(size_t)MM*DIF];   // scan out (half)
__device__ __align__(8)  __half2 g_dg [4][(size_t)MM*DIF];   // (dv, gate) per step
__device__ float  g_hf  [4*8*NSEG*DIF*16];            // per-segment final h
__device__ float  g_sdv [4*8*NSEG*DIF];               // per-segment sum(dv)
__device__ float  g_o   [2][(size_t)MM*DMF];          // fused GEMM4 out (2 pairs)
// transposed + half weights: [w][n][k]
__device__ __align__(16) __half g_wt1[8*1024*256];
__device__ __align__(16) __half g_wt2[8*64*512];
__device__ __align__(16) __half g_wt4[8*256*512];

__device__ __forceinline__ float siluf(float x){ return x / (1.f + __expf(-x)); }

// ---------------- PTX helpers ----------------------------------------------
__device__ __forceinline__ void mma_f16(float* c, const uint32_t* a, const uint32_t* b){
  asm volatile(
    "mma.sync.aligned.m16n8k16.row.col.f32.f16.f16.f32 "
    "{%0,%1,%2,%3}, {%4,%5,%6,%7}, {%8,%9}, {%0,%1,%2,%3};\n"
    : "+f"(c[0]), "+f"(c[1]), "+f"(c[2]), "+f"(c[3])
    : "r"(a[0]), "r"(a[1]), "r"(a[2]), "r"(a[3]), "r"(b[0]), "r"(b[1]));
}
__device__ __forceinline__ void ldsm4(uint32_t* r, uint32_t addr){
  asm volatile("ldmatrix.sync.aligned.m8n8.x4.shared.b16 {%0,%1,%2,%3}, [%4];"
    : "=r"(r[0]), "=r"(r[1]), "=r"(r[2]), "=r"(r[3]) : "r"(addr));
}
__device__ __forceinline__ void cpa16(uint32_t dst, const void* src){
  asm volatile("cp.async.cg.shared.global [%0], [%1], 16;" :: "r"(dst), "l"(src));
}

// ---------------- weight transpose + fp16 convert ---------------------------
__global__ void wtrans_ker(const float* __restrict__ ip, const float* __restrict__ xp,
                           const float* __restrict__ op){
  int s = blockIdx.z >> 3;
  int w = blockIdx.z & 7;
  int K = (s==0)?256:512;
  int N = (s==0)?1024:((s==1)?48:256);
  int Nout = (s==1)?64:N;
  const float* src = (s==0)?ip:((s==1)?xp:op);
  __half* dst = (s==0)?g_wt1:((s==1)?g_wt2:g_wt4);
  src += (size_t)w*K*N; dst += (size_t)w*(size_t)Nout*K;
  int k0 = blockIdx.x*32, n0 = blockIdx.y*32;
  if (k0 >= K || n0 >= Nout) return;
  __shared__ float tile[32][33];
  int tx = threadIdx.x, ty = threadIdx.y;
  for (int i = ty; i < 32; i += 8){
    int k = k0+i, n = n0+tx;
    tile[i][tx] = (k < K && n < N) ? src[(size_t)k*N + n] : 0.f;
  }
  __syncthreads();
  for (int i = ty; i < 32; i += 8){
    int n = n0+i, k = k0+tx;
    if (n < Nout && k < K) dst[(size_t)n*K + k] = __float2half(tile[tx][i]);
  }
}

// ---------------- elementwise kernels --------------------------------------
__global__ void add_pe_ker(const float* __restrict__ x, const float* __restrict__ pe){
  int i = blockIdx.x, c = threadIdx.x;
  int t = i % Tt;
  float v = x[(size_t)i*DMF + c] + pe[t*DMF + c];
  g_x [(size_t)i*DMF + c] = v;
  g_xh[(size_t)i*DMF + c] = __float2half(v);
}

// ---------------- fp16 tensor-core GEMM (ldmatrix + cp.async) --------------
#define STRH 40
#define ABUF (128*STRH)
template<int NT>
__global__ void __launch_bounds__(256) hgemm_ker(
    const __half* __restrict__ A0, size_t zstr,
    const __half* __restrict__ WtB, void* __restrict__ Cb,
    int K, int Ntot, int l, int perm, int hout)
{
  constexpr int BBUF = NT*STRH;
  extern __shared__ __half smh[];
  const uint32_t sb = (uint32_t)__cvta_generic_to_shared(smh);
  const uint32_t aOff[2] = {0u, (uint32_t)ABUF*2u};
  const uint32_t bOff[2] = {(uint32_t)(2*ABUF)*2u, (uint32_t)(2*ABUF + BBUF)*2u};

  const int z = blockIdx.z;
  const __half* A = A0 + (size_t)z*zstr;
  const int n0 = blockIdx.y * NT;
  const int Nrows = (Ntot==48) ? 64 : Ntot;
  const __half* Wt = WtB + ((size_t)(l*4 + z)*Nrows + n0) * K;

  const int tid  = threadIdx.x;
  const int lane = tid & 31;
  const int w    = tid >> 5;
  constexpr int WN = NT/4;
  constexpr int NATOMS = WN/8;
  constexpr int NPAIRS = WN/16;
  const int wm = (w & 1) * 64;
  const int wn = (w >> 1) * WN;
  const int row0 = blockIdx.x * 128;

  float acc[4][NATOMS][4];
  #pragma unroll
  for (int ma = 0; ma < 4; ma++)
    #pragma unroll
    for (int na = 0; na < NATOMS; na++)
      #pragma unroll
      for (int q = 0; q < 4; q++) acc[ma][na][q] = 0.f;

  const int a_r = tid >> 1;
  const int a_u = (tid & 1) * 2;
  int grow = row0 + a_r;
  if (perm && z >= 2){
    int b2 = grow / LL;
    int p  = grow - b2*LL;
    int tq = p / Oo;
    int o  = p - tq*Oo;
    grow = b2*LL + o*Tt + tq;
  }
  const __half* Arow = A + (size_t)grow*K;

  const uint32_t aLd = (uint32_t)((wm + (lane & 15))*STRH + (lane >> 4)*8) * 2u;
  const int nloc = ((lane & 16) >> 1) | (lane & 7);
  const uint32_t bLd = (uint32_t)((wn + nloc)*STRH + ((lane >> 3) & 1)*8) * 2u;

  auto load_chunk = [&](int buf, int c){
    const int kb = c*32;
    const uint32_t ab = sb + aOff[buf];
    const uint32_t bb = sb + bOff[buf];
    #pragma unroll
    for (int u = 0; u < 2; u++)
      cpa16(ab + (uint32_t)(a_r*STRH + (a_u+u)*8)*2u, Arow + kb + (a_u+u)*8);
    #pragma unroll
    for (int it = 0; it < NT/64; it++){
      int idx = tid + it*256;
      int r = idx >> 2, u = idx & 3;
      cpa16(bb + (uint32_t)(r*STRH + u*8)*2u, &Wt[(size_t)r*K + kb + u*8]);
    }
    asm volatile("cp.async.commit_group;" ::: "memory");
  };

  auto compute = [&](int buf){
    const uint32_t ab = sb + aOff[buf];
    const uint32_t bb = sb + bOff[buf];
    #pragma unroll
    for (int ks = 0; ks < 2; ks++){
      uint32_t af[4][4];
      #pragma unroll
      for (int ma = 0; ma < 4; ma++)
        ldsm4(af[ma], ab + aLd + (uint32_t)(ma*16*STRH + ks*16)*2u);
      uint32_t bf[2*NPAIRS][2];
      #pragma unroll
      for (int np = 0; np < NPAIRS; np++){
        uint32_t r4[4];
        ldsm4(r4, bb + bLd + (uint32_t)(np*16*STRH + ks*16)*2u);
        bf[np*2+0][0] = r4[0]; bf[np*2+0][1] = r4[1];
        bf[np*2+1][0] = r4[2]; bf[np*2+1][1] = r4[3];
      }
      #pragma unroll
      for (int ma = 0; ma < 4; ma++)
        #pragma unroll
        for (int na = 0; na < NATOMS; na++)
          mma_f16(acc[ma][na], af[ma], bf[na]);
    }
  };

  const int nc = K / 32;
  load_chunk(0, 0);
  for (int c = 0; c < nc; c++){
    const int buf = c & 1;
    if (c + 1 < nc){
      load_chunk(buf ^ 1, c + 1);
      asm volatile("cp.async.wait_group 1;" ::: "memory");
    } else {
      asm volatile("cp.async.wait_group 0;" ::: "memory");
    }
    __syncthreads();
    compute(buf);
    __syncthreads();
  }

  if (hout){
    __half* Ch = (__half*)Cb + (size_t)z * (size_t)MM * Ntot;
    #pragma unroll
    for (int ma = 0; ma < 4; ma++){
      const int r = row0 + wm + ma*16 + (lane >> 2);
      #pragma unroll
      for (int na = 0; na < NATOMS; na++){
        const int cc = n0 + wn + na*8 + (lane & 3)*2;
        if (cc < Ntot){
          *reinterpret_cast<__half2*>(&Ch[(size_t)r*Ntot + cc])     = __floats2half2_rn(acc[ma][na][0], acc[ma][na][1]);
          *reinterpret_cast<__half2*>(&Ch[(size_t)(r+8)*Ntot + cc]) = __floats2half2_rn(acc[ma][na][2], acc[ma][na][3]);
        }
      }
    }
  } else {
    float* C = (float*)Cb + (size_t)z * (size_t)MM * Ntot;
    #pragma unroll
    for (int ma = 0; ma < 4; ma++){
      const int r = row0 + wm + ma*16 + (lane >> 2);
      #pragma unroll
      for (int na = 0; na < NATOMS; na++){
        const int cc = n0 + wn + na*8 + (lane & 3)*2;
        if (cc < Ntot){
          *reinterpret_cast<float2*>(&C[(size_t)r*Ntot + cc])     = make_float2(acc[ma][na][0], acc[ma][na][1]);
          *reinterpret_cast<float2*>(&C[(size_t)(r+8)*Ntot + cc]) = make_float2(acc[ma][na][2], acc[ma][na][3]);
        }
      }
    }
  }
}

// ---------------- fused out-proj pair GEMM: o[p] = [u(2p),u(2p+1)] @ [W;W] --
__global__ void __launch_bounds__(256) hgemm_pair_ker(int l){
  constexpr int NT = 128;
  constexpr int BBUF = NT*STRH;
  extern __shared__ __half smh[];
  const uint32_t sb = (uint32_t)__cvta_generic_to_shared(smh);
  const uint32_t aOff[2] = {0u, (uint32_t)ABUF*2u};
  const uint32_t bOff[2] = {(uint32_t)(2*ABUF)*2u, (uint32_t)(2*ABUF + BBUF)*2u};

  const int p = blockIdx.z;
  const int n0 = blockIdx.y * NT;
  const int tid  = threadIdx.x;
  const int lane = tid & 31;
  const int w    = tid >> 5;
  const int wm = (w & 1) * 64;
  const int wn = (w >> 1) * 32;
  const int row0 = blockIdx.x * 128;

  const __half* Alo = g_uh[p*2];
  const __half* Ahi = g_uh[p*2+1];
  const __half* Wlo = g_wt4 + (size_t)(l*4 + p*2    )*256*512;
  const __half* Whi = g_wt4 + (size_t)(l*4 + p*2 + 1)*256*512;

  float acc[4][4][4];
  #pragma unroll
  for (int ma = 0; ma < 4; ma++)
    #pragma unroll
    for (int na = 0; na < 4; na++)
      #pragma unroll
      for (int q = 0; q < 4; q++) acc[ma][na][q] = 0.f;

  const int a_r = tid >> 1;
  const int a_u = (tid & 1) * 2;
  const int grow = row0 + a_r;

  const uint32_t aLd = (uint32_t)((wm + (lane & 15))*STRH + (lane >> 4)*8) * 2u;
  const int nloc = ((lane & 16) >> 1) | (lane & 7);
  const uint32_t bLd = (uint32_t)((wn + nloc)*STRH + ((lane >> 3) & 1)*8) * 2u;

  auto load_chunk = [&](int buf, int c){
    const int kb = c*32;
    const bool hi = (kb >= 512);
    const int kk = hi ? (kb - 512) : kb;
    const __half* Asrc = (hi ? Ahi : Alo) + (size_t)grow*DIF + kk;
    const __half* Wsrc = (hi ? Whi : Wlo);
    const uint32_t ab = sb + aOff[buf];
    const uint32_t bb = sb + bOff[buf];
    #pragma unroll
    for (int u = 0; u < 2; u++)
      cpa16(ab + (uint32_t)(a_r*STRH + (a_u+u)*8)*2u, Asrc + (a_u+u)*8);
    #pragma unroll
    for (int it = 0; it < 2; it++){
      int idx = tid + it*256;
      int r = idx >> 2, u = idx & 3;
      cpa16(bb + (uint32_t)(r*STRH + u*8)*2u,
            &Wsrc[(size_t)(n0 + r)*512 + kk + u*8]);
    }
    asm volatile("cp.async.commit_group;" ::: "memory");
  };

  auto compute = [&](int buf){
    const uint32_t ab = sb + aOff[buf];
    const uint32_t bb = sb + bOff[buf];
    #pragma unroll
    for (int ks = 0; ks < 2; ks++){
      uint32_t af[4][4];
      #pragma unroll
      for (int ma = 0; ma < 4; ma++)
        ldsm4(af[ma], ab + aLd + (uint32_t)(ma*16*STRH + ks*16)*2u);
      uint32_t bf[4][2];
      #pragma unroll
      for (int np = 0; np < 2; np++){
        uint32_t r4[4];
        ldsm4(r4, bb + bLd + (uint32_t)(np*16*STRH + ks*16)*2u);
        bf[np*2+0][0] = r4[0]; bf[np*2+0][1] = r4[1];
        bf[np*2+1][0] = r4[2]; bf[np*2+1][1] = r4[3];
      }
      #pragma unroll
      for (int ma = 0; ma < 4; ma++)
        #pragma unroll
        for (int na = 0; na < 4; na++)
          mma_f16(acc[ma][na], af[ma], bf[na]);
    }
  };

  const int nc = 1024 / 32;
  load_chunk(0, 0);
  for (int c = 0; c < nc; c++){
    const int buf = c & 1;
    if (c + 1 < nc){
      load_chunk(buf ^ 1, c + 1);
      asm volatile("cp.async.wait_group 1;" ::: "memory");
    } else {
      asm volatile("cp.async.wait_group 0;" ::: "memory");
    }
    __syncthreads();
    compute(buf);
    __syncthreads();
  }

  float* C = g_o[p];
  #pragma unroll
  for (int ma = 0; ma < 4; ma++){
    const int r = row0 + wm + ma*16 + (lane >> 2);
    #pragma unroll
    for (int na = 0; na < 4; na++){
      const int cc = n0 + wn + na*8 + (lane & 3)*2;
      *reinterpret_cast<float2*>(&C[(size_t)r*DMF + cc])     = make_float2(acc[ma][na][0], acc[ma][na][1]);
      *reinterpret_cast<float2*>(&C[(size_t)(r+8)*DMF + cc]) = make_float2(acc[ma][na][2], acc[ma][na][3]);
    }
  }
}

// ---------------- depthwise causal conv + SiLU (half in/out, 4 t/thread) ---
__global__ void conv_ker(const float* __restrict__ conv_w, const float* __restrict__ conv_b, int l){
  int z   = blockIdx.y;
  int gid = blockIdx.x*256 + threadIdx.x;
  const int NT4 = LL/4;
  int i4 = gid / (DIF/4);
  int dq = gid % (DIF/4);
  int d  = dq*4;
  int b  = i4 / NT4;
  int t0 = (i4 - b*NT4)*4;
  int widx = l*4 + z;
  const __half* xz = g_xzh[z];

  float wv[4][4], bi[4];
  #pragma unroll
  for (int di = 0; di < 4; di++){
    float4 w4 = *reinterpret_cast<const float4*>(&conv_w[(size_t)(widx*DIF + d+di)*4]);
    wv[di][0]=w4.x; wv[di][1]=w4.y; wv[di][2]=w4.z; wv[di][3]=w4.w;
  }
  {
    float4 b4 = *reinterpret_cast<const float4*>(&conv_b[(size_t)widx*DIF + d]);
    bi[0]=b4.x; bi[1]=b4.y; bi[2]=b4.z; bi[3]=b4.w;
  }
  size_t base = (size_t)b*LL;
  float v[7][4];
  bool fwd = ((z & 1) == 0);
  #pragma unroll
  for (int j = 0; j < 7; j++){
    int tt = fwd ? (t0 + j - 3) : (t0 + j);
    if (tt >= 0 && tt < LL){
      const __half2* p2 = reinterpret_cast<const __half2*>(&xz[(base+tt)*1024 + d]);
      float2 a = __half22float2(p2[0]), c2 = __half22float2(p2[1]);
      v[j][0]=a.x; v[j][1]=a.y; v[j][2]=c2.x; v[j][3]=c2.y;
    } else {
      v[j][0]=v[j][1]=v[j][2]=v[j][3]=0.f;
    }
  }
  #pragma unroll
  for (int k = 0; k < 4; k++){
    float o[4];
    #pragma unroll
    for (int di = 0; di < 4; di++){
      float s = bi[di];
      if (fwd){
        #pragma unroll
        for (int i2 = 0; i2 < 4; i2++) s = fmaf(wv[di][i2], v[k+i2][di], s);
      } else {
        #pragma unroll
        for (int j = 0; j < 4; j++)    s = fmaf(wv[di][3-j], v[k+j][di], s);
      }
      o[di] = siluf(s);
    }
    __half2* oh = reinterpret_cast<__half2*>(&g_xch[z][(base + t0 + k)*DIF + d]);
    oh[0] = __floats2half2_rn(o[0], o[1]);
    oh[1] = __floats2half2_rn(o[2], o[3]);
  }
}

// ---------------- scan phase 1: per-segment local scan (h0 = 0) ------------
#define S1CH 32
#define oDBL 0
#define oXC  12288
#define oZ   28672
#define S1_SMEM 45056
__global__ void __launch_bounds__(128) scan1_ker(const float* __restrict__ A_log,
                                                 const float* __restrict__ Dp,
                                                 const float* __restrict__ dtw,
                                                 const float* __restrict__ dtb, int l){
  extern __shared__ char ssm[];
  const uint32_t sb = (uint32_t)__cvta_generic_to_shared(ssm);
  int tid = threadIdx.x;
  int d0 = blockIdx.x*128, d = d0 + tid;
  int b = blockIdx.y;
  int z = blockIdx.z >> 3, seg = blockIdx.z & 7;
  int widx = l*4 + z;
  bool bwd = (z & 1);
  const __half* xch = g_xch[z];
  const __half* xzz = g_xzh[z];
  const float*  dbl = g_dbl[z];
  __half*  u  = g_uh[z];
  __half2* dg = g_dg[z];

  float W[16];
  #pragma unroll
  for (int k = 0; k < 16; k++) W[k] = dtw[((size_t)widx*16 + k)*DIF + d];
  float bia = dtb[(size_t)widx*DIF + d];
  float Av[16];
  #pragma unroll
  for (int s = 0; s < 16; s++)
    Av[s] = -expf(A_log[((size_t)widx*DIF + d)*DSF + s]);
  bool pc = true;
  #pragma unroll
  for (int s = 1; s < 16; s++)
    pc = pc && (fabsf(Av[s] - (float)(s+1)*Av[0]) <= 1e-4f * fabsf(Av[s]));
  float Dpar = Dp[(size_t)widx*DIF + d];

  float h[16];
  #pragma unroll
  for (int s = 0; s < 16; s++) h[s] = 0.f;
  float sumdv = 0.f;
  const int gi0 = seg*LSEG;

  auto load_chunk = [&](int c, int buf){
    #pragma unroll
    for (int it = 0; it < 3; it++){
      int idx = tid + it*128;
      int ls = idx / 12, q = idx - ls*12;
      int gi = gi0 + c*S1CH + ls;
      int t = bwd ? (LL-1 - gi) : gi;
      cpa16(sb + oDBL + (uint32_t)(((buf*S1CH + ls)*12 + q)*16),
            &dbl[(size_t)(b*LL + t)*48 + q*4]);
    }
    #pragma unroll
    for (int it = 0; it < 4; it++){
      int idx = tid + it*128;
      int ls = idx >> 4, sg = idx & 15;
      int gi = gi0 + c*S1CH + ls;
      int t = bwd ? (LL-1 - gi) : gi;
      cpa16(sb + oXC + (uint32_t)(((buf*S1CH + ls)*128 + sg*8)*2),
            &xch[(size_t)(b*LL + t)*DIF + d0 + sg*8]);
      cpa16(sb + oZ + (uint32_t)(((buf*S1CH + ls)*128 + sg*8)*2),
            &xzz[(size_t)(b*LL + t)*1024 + DIF + d0 + sg*8]);
    }
    asm volatile("cp.async.commit_group;" ::: "memory");
  };

  const int nc = LSEG / S1CH;   // 3
  load_chunk(0, 0);
  for (int c = 0; c < nc; c++){
    const int buf = c & 1;
    if (c + 1 < nc){
      load_chunk(c + 1, buf ^ 1);
      asm volatile("cp.async.wait_group 1;" ::: "memory");
    } else {
      asm volatile("cp.async.wait_group 0;" ::: "memory");
    }
    __syncthreads();
    const float4* sD = reinterpret_cast<const float4*>(ssm + oDBL) + (size_t)buf*S1CH*12;
    const __half* sX = reinterpret_cast<const __half*>(ssm + oXC) + (size_t)buf*S1CH*128;
    const __half* sZ = reinterpret_cast<const __half*>(ssm + oZ)  + (size_t)buf*S1CH*128;

    for (int ls = 0; ls < S1CH; ls++){
      int gi = gi0 + c*S1CH + ls;
      int t  = bwd ? (LL-1 - gi) : gi;
      float xcv = __half2float(sX[ls*128 + tid]);
      float zv  = __half2float(sZ[ls*128 + tid]);
      const float4* row = sD + ls*12;
      float4 q0 = row[0], q1 = row[1], q2 = row[2], q3 = row[3];
      float a0 = fmaf(q0.x, W[0],  fmaf(q0.y, W[1],  fmaf(q0.z, W[2],  q0.w*W[3])));
      float a1 = fmaf(q1.x, W[4],  fmaf(q1.y, W[5],  fmaf(q1.z, W[6],  q1.w*W[7])));
      float a2 = fmaf(q2.x, W[8],  fmaf(q2.y, W[9],  fmaf(q2.z, W[10], q2.w*W[11])));
      float a3 = fmaf(q3.x, W[12], fmaf(q3.y, W[13], fmaf(q3.z, W[14], q3.w*W[15])));
      float a = bia + ((a0 + a1) + (a2 + a3));
      float dv = fmaxf(a, 0.f) + log1pf(__expf(-fabsf(a)));
      sumdv += dv;
      float du = dv * xcv;

      float acc0 = 0.f, acc1 = 0.f, acc2 = 0.f, acc3 = 0.f;
      if (pc){
        float e1 = __expf(dv * Av[0]);
        float e2 = e1*e1, e3 = e2*e1, e4 = e2*e2;
        float e5 = e4*e1, e6 = e4*e2, e7 = e4*e3, e8 = e4*e4;
        float e9 = e8*e1, e10 = e8*e2, e11 = e8*e3, e12 = e8*e4;
        float e13 = e8*e5, e14 = e8*e6, e15 = e8*e7, e16 = e8*e8;
        float4 B0 = row[4], B1 = row[5], B2 = row[6], B3 = row[7];
        float4 C0 = row[8], C1 = row[9], C2 = row[10], C3 = row[11];
        h[0]  = fmaf(e1,  h[0],  du*B0.x); acc0 = fmaf(h[0],  C0.x, acc0);
        h[1]  = fmaf(e2,  h[1],  du*B0.y); acc1 = fmaf(h[1],  C0.y, acc1);
        h[2]  = fmaf(e3,  h[2],  du*B0.z); acc2 = fmaf(h[2],  C0.z, acc2);
        h[3]  = fmaf(e4,  h[3],  du*B0.w); acc3 = fmaf(h[3],  C0.w, acc3);
        h[4]  = fmaf(e5,  h[4],  du*B1.x); acc0 = fmaf(h[4],  C1.x, acc0);
        h[5]  = fmaf(e6,  h[5],  du*B1.y); acc1 = fmaf(h[5],  C1.y, acc1);
        h[6]  = fmaf(e7,  h[6],  du*B1.z); acc2 = fmaf(h[6],  C1.z, acc2);
        h[7]  = fmaf(e8,  h[7],  du*B1.w); acc3 = fmaf(h[7],  C1.w, acc3);
        h[8]  = fmaf(e9,  h[8],  du*B2.x); acc0 = fmaf(h[8],  C2.x, acc0);
        h[9]  = fmaf(e10, h[9],  du*B2.y); acc1 = fmaf(h[9],  C2.y, acc1);
        h[10] = fmaf(e11, h[10], du*B2.z); acc2 = fmaf(h[10], C2.z, acc2);
        h[11] = fmaf(e12, h[11], du*B2.w); acc3 = fmaf(h[11], C2.w, acc3);
        h[12] = fmaf(e13, h[12], du*B3.x); acc0 = fmaf(h[12], C3.x, acc0);
        h[13] = fmaf(e14, h[13], du*B3.y); acc1 = fmaf(h[13], C3.y, acc1);
        h[14] = fmaf(e15, h[14], du*B3.z); acc2 = fmaf(h[14], C3.z, acc2);
        h[15] = fmaf(e16, h[15], du*B3.w); acc3 = fmaf(h[15], C3.w, acc3);
      } else {
        #pragma unroll
        for (int q = 0; q < 4; q++){
          float4 B4 = row[4+q];
          float4 C4 = row[8+q];
          float b0 = __expf(dv*Av[q*4+0]); h[q*4+0] = fmaf(b0, h[q*4+0], du*B4.x); acc0 = fmaf(h[q*4+0], C4.x, acc0);
          float b1 = __expf(dv*Av[q*4+1]); h[q*4+1] = fmaf(b1, h[q*4+1], du*B4.y); acc1 = fmaf(h[q*4+1], C4.y, acc1);
          float b2 = __expf(dv*Av[q*4+2]); h[q*4+2] = fmaf(b2, h[q*4+2], du*B4.z); acc2 = fmaf(h[q*4+2], C4.z, acc2);
          float b3 = __expf(dv*Av[q*4+3]); h[q*4+3] = fmaf(b3, h[q*4+3], du*B4.w); acc3 = fmaf(h[q*4+3], C4.w, acc3);
        }
      }
      float gate = siluf(zv);
      float y = (acc0 + acc1) + (acc2 + acc3) + xcv * Dpar;
      size_t rowd = (size_t)(b*LL + t)*DIF + d;
      u[rowd]  = __float2half(y * gate);
      dg[rowd] = __floats2half2_rn(dv, gate);
    }
    __syncthreads();
  }
  int segbase = ((z*8 + b)*NSEG + seg)*DIF + d;
  float4* hf4 = reinterpret_cast<float4*>(&g_hf[(size_t)segbase*16]);
  hf4[0] = make_float4(h[0],  h[1],  h[2],  h[3]);
  hf4[1] = make_float4(h[4],  h[5],  h[6],  h[7]);
  hf4[2] = make_float4(h[8],  h[9],  h[10], h[11]);
  hf4[3] = make_float4(h[12], h[13], h[14], h[15]);
  g_sdv[segbase] = sumdv;
}

// ---------------- scan phase 2: cross-segment correction (early exit) ------
#define S2CH 32
#define oC2  0
#define oDG2 4096
#define oU2  36864
#define S2_SMEM 53248
__global__ void __launch_bounds__(128) scan2_ker(const float* __restrict__ A_log, int l){
  extern __shared__ char ssm[];
  const uint32_t sb = (uint32_t)__cvta_generic_to_shared(ssm);
  int tid = threadIdx.x;
  int d0 = blockIdx.x*128, d = d0 + tid;
  int b = blockIdx.y;
  int z = blockIdx.z / (NSEG-1), seg = blockIdx.z - z*(NSEG-1) + 1;
  int widx = l*4 + z;
  bool bwd = (z & 1);
  const float*  dbl = g_dbl[z];
  const __half2* dg = g_dg[z];
  __half* u = g_uh[z];

  float Av[16];
  #pragma unroll
  for (int s = 0; s < 16; s++)
    Av[s] = -expf(A_log[((size_t)widx*DIF + d)*DSF + s]);
  bool pc = true;
  #pragma unroll
  for (int s = 1; s < 16; s++)
    pc = pc && (fabsf(Av[s] - (float)(s+1)*Av[0]) <= 1e-4f * fabsf(Av[s]));
  float amax = Av[0];
  #pragma unroll
  for (int s = 1; s < 16; s++) amax = fmaxf(amax, Av[s]);

  float hin[16];
  #pragma unroll
  for (int s = 0; s < 16; s++) hin[s] = 0.f;
  for (int k = 0; k < seg; k++){
    int kb = ((z*8 + b)*NSEG + k)*DIF + d;
    float sd = g_sdv[kb];
    const float4* hf4 = reinterpret_cast<const float4*>(&g_hf[(size_t)kb*16]);
    float4 f0 = hf4[0], f1 = hf4[1], f2 = hf4[2], f3 = hf4[3];
    float hf[16] = {f0.x,f0.y,f0.z,f0.w, f1.x,f1.y,f1.z,f1.w,
                    f2.x,f2.y,f2.z,f2.w, f3.x,f3.y,f3.z,f3.w};
    if (pc){
      float E = __expf(Av[0]*sd);
      float p = 1.f;
      #pragma unroll
      for (int s = 0; s < 16; s++){ p *= E; hin[s] = fmaf(p, hin[s], hf[s]); }
    } else {
      #pragma unroll
      for (int s = 0; s < 16; s++) hin[s] = fmaf(__expf(Av[s]*sd), hin[s], hf[s]);
    }
  }

  const int gi0 = seg*LSEG;
  auto load_chunk = [&](int c, int buf){
    {
      int ls = tid >> 2, q = tid & 3;
      int gi = gi0 + c*S2CH + ls;
      int t = bwd ? (LL-1 - gi) : gi;
      cpa16(sb + oC2 + (uint32_t)(((buf*S2CH + ls)*4 + q)*16),
            &dbl[(size_t)(b*LL + t)*48 + 32 + q*4]);
    }
    #pragma unroll
    for (int it = 0; it < 8; it++){
      int idx = tid + it*128;
      int ls = idx >> 5, sg = idx & 31;
      int gi = gi0 + c*S2CH + ls;
      int t = bwd ? (LL-1 - gi) : gi;
      cpa16(sb + oDG2 + (uint32_t)(((buf*S2CH + ls)*128 + sg*4)*4),
            &dg[(size_t)(b*LL + t)*DIF + d0 + sg*4]);
    }
    #pragma unroll
    for (int it = 0; it < 4; it++){
      int idx = tid + it*128;
      int ls = idx >> 4, sg = idx & 15;
      int gi = gi0 + c*S2CH + ls;
      int t = bwd ? (LL-1 - gi) : gi;
      cpa16(sb + oU2 + (uint32_t)(((buf*S2CH + ls)*128 + sg*8)*2),
            &u[(size_t)(b*LL + t)*DIF + d0 + sg*8]);
    }
    asm volatile("cp.async.commit_group;" ::: "memory");
  };

  float cacc = 0.f;
  const int nc = LSEG / S2CH;   // 3
  load_chunk(0, 0);
  for (int c = 0; c < nc; c++){
    const int buf = c & 1;
    if (c + 1 < nc){
      load_chunk(c + 1, buf ^ 1);
      asm volatile("cp.async.wait_group 1;" ::: "memory");
    } else {
      asm volatile("cp.async.wait_group 0;" ::: "memory");
    }
    __syncthreads();
    const float4*  sC = reinterpret_cast<const float4*>(ssm + oC2) + (size_t)buf*S2CH*4;
    const __half2* sG = reinterpret_cast<const __half2*>(ssm + oDG2) + (size_t)buf*S2CH*128;
    const __half*  sU = reinterpret_cast<const __half*>(ssm + oU2) + (size_t)buf*S2CH*128;

    for (int ls = 0; ls < S2CH; ls++){
      int gi = gi0 + c*S2CH + ls;
      int t  = bwd ? (LL-1 - gi) : gi;
      float2 dgv = __half22float2(sG[ls*128 + tid]);
      cacc += dgv.x;
      float4 C0 = sC[ls*4+0], C1 = sC[ls*4+1], C2 = sC[ls*4+2], C3 = sC[ls*4+3];
      float corr;
      if (pc){
        float e1 = __expf(Av[0]*cacc);
        float e2 = e1*e1, e3 = e2*e1, e4 = e2*e2;
        float e5 = e4*e1, e6 = e4*e2, e7 = e4*e3, e8 = e4*e4;
        float e9 = e8*e1, e10 = e8*e2, e11 = e8*e3, e12 = e8*e4;
        float e13 = e8*e5, e14 = e8*e6, e15 = e8*e7, e16 = e8*e8;
        float c0 = fmaf(e1*hin[0],  C0.x, 0.f);
        c0 = fmaf(e5*hin[4],  C1.x, c0);
        c0 = fmaf(e9*hin[8],  C2.x, c0);
        c0 = fmaf(e13*hin[12], C3.x, c0);
        float c1 = fmaf(e2*hin[1],  C0.y, 0.f);
        c1 = fmaf(e6*hin[5],  C1.y, c1);
        c1 = fmaf(e10*hin[9], C2.y, c1);
        c1 = fmaf(e14*hin[13], C3.y, c1);
        float c2 = fmaf(e3*hin[2],  C0.z, 0.f);
        c2 = fmaf(e7*hin[6],  C1.z, c2);
        c2 = fmaf(e11*hin[10], C2.z, c2);
        c2 = fmaf(e15*hin[14], C3.z, c2);
        float c3 = fmaf(e4*hin[3],  C0.w, 0.f);
        c3 = fmaf(e8*hin[7],  C1.w, c3);
        c3 = fmaf(e12*hin[11], C2.w, c3);
        c3 = fmaf(e16*hin[15], C3.w, c3);
        corr = (c0 + c1) + (c2 + c3);
      } else {
        float Cw[16] = {C0.x,C0.y,C0.z,C0.w, C1.x,C1.y,C1.z,C1.w,
                        C2.x,C2.y,C2.z,C2.w, C3.x,C3.y,C3.z,C3.w};
        corr = 0.f;
        #pragma unroll
        for (int s = 0; s < 16; s++)
          corr = fmaf(__expf(Av[s]*cacc)*hin[s], Cw[s], corr);
      }
      float up = __half2float(sU[ls*128 + tid]);
      u[(size_t)(b*LL + t)*DIF + d] = __float2half(fmaf(corr, dgv.y, up));
    }
    int done = (cacc * (-amax) > 25.f) ? 1 : 0;
    if (__syncthreads_and(done)){
      asm volatile("cp.async.wait_group 0;" ::: "memory");
      break;
    }
  }
}

// ---------------- combine: LN(o0), LN(o1), residual add; optional out ------
__global__ void combine_ker(const float* __restrict__ lnw, const float* __restrict__ lnb,
                            float* __restrict__ out, int last){
  int i = blockIdx.x, c = threadIdx.x;
  float a  = g_o[0][(size_t)i*DMF + c];
  float bv = g_o[1][(size_t)i*DMF + c];
  __shared__ float r1[256], r2[256];
  r1[c] = a; r2[c] = bv; __syncthreads();
  for (int s = 128; s > 0; s >>= 1){
    if (c < s){ r1[c] += r1[c+s]; r2[c] += r2[c+s]; }
    __syncthreads();
  }
  float ma = r1[0] * (1.f/DMF), mb = r2[0] * (1.f/DMF);
  __syncthreads();
  float da = a - ma, db = bv - mb;
  r1[c] = da*da; r2[c] = db*db; __syncthreads();
  for (int s = 128; s > 0; s >>= 1){
    if (c < s){ r1[c] += r1[c+s]; r2[c] += r2[c+s]; }
    __syncthreads();
  }
  float va = r1[0] * (1.f/DMF), vb = r2[0] * (1.f/DMF);
  float s1 = da * rsqrtf(va + 1e-5f) * lnw[c] + lnb[c];
  float s2 = db * rsqrtf(vb + 1e-5f) * lnw[c] + lnb[c];
  float nv = g_x[(size_t)i*DMF + c] + 0.5f * (s1 + s2);
  g_x [(size_t)i*DMF + c] = nv;
  g_xh[(size_t)i*DMF + c] = __float2half(nv);
  if (last) out[(size_t)i*DMF + c] = nv;
}

// ---------------- host orchestration ---------------------------------------
#define SMEM_H128 ((2*ABUF + 2*128*STRH)*2)   // 40960 B
#define SMEM_H64  ((2*ABUF + 2*64*STRH)*2)    // 30720 B

extern "C" void kernel_launch(void* const* d_in, const int* in_sizes, int n_in,
                              void* d_out, int out_size){
  const float* x       = (const float*)d_in[0];
  const float* pe      = (const float*)d_in[1];
  const float* ln_w    = (const float*)d_in[2];
  const float* ln_b    = (const float*)d_in[3];
  const float* in_proj = (const float*)d_in[4];
  const float* conv_w  = (const float*)d_in[5];
  const float* conv_b  = (const float*)d_in[6];
  const float* x_proj  = (const float*)d_in[7];
  const float* dt_w    = (const float*)d_in[8];
  const float* dt_b    = (const float*)d_in[9];
  const float* A_log   = (const float*)d_in[10];
  const float* Dp      = (const float*)d_in[11];
  const float* out_prj = (const float*)d_in[12];

  void *pxh, *pxzh, *pxch, *pdbl, *pw1, *pw2;
  cudaGetSymbolAddress(&pxh,  g_xh);
  cudaGetSymbolAddress(&pxzh, g_xzh);
  cudaGetSymbolAddress(&pxch, g_xch);
  cudaGetSymbolAddress(&pdbl, g_dbl);
  cudaGetSymbolAddress(&pw1,  g_wt1);
  cudaGetSymbolAddress(&pw2,  g_wt2);

  cudaFuncSetAttribute(scan1_ker, cudaFuncAttributeMaxDynamicSharedMemorySize, S1_SMEM);
  cudaFuncSetAttribute(scan2_ker, cudaFuncAttributeMaxDynamicSharedMemorySize, S2_SMEM);

  wtrans_ker<<<dim3(16, 32, 24), dim3(32, 8)>>>(in_proj, x_proj, out_prj);
  add_pe_ker<<<MM, 256>>>(x, pe);

  for (int l = 0; l < NLAY; l++){
    // GEMM1: xz[z] = seq(z) @ in_proj[l,z]  (N=1024, K=256, half out)
    hgemm_ker<128><<<dim3(MM/128, 8, 4), 256, SMEM_H128>>>(
        (const __half*)pxh, (size_t)0,
        (const __half*)pw1, pxzh, 256, 1024, l, 1, 1);
    conv_ker<<<dim3((MM/4)*(DIF/4)/256, 4), 256>>>(conv_w, conv_b, l);
    // GEMM2: dbl[z] = xc[z] @ x_proj (N=48 pad 64, K=512, fp32 out)
    hgemm_ker<64><<<dim3(MM/128, 1, 4), 256, SMEM_H64>>>(
        (const __half*)pxch, (size_t)MM*DIF,
        (const __half*)pw2, pdbl, 512, 48, l, 0, 0);
    // selective scan: 8-segment phase 1 (chunk 32) + early-exit fixup
    scan1_ker<<<dim3(4, Bb, 4*NSEG), 128, S1_SMEM>>>(A_log, Dp, dt_w, dt_b, l);
    scan2_ker<<<dim3(4, Bb, 4*(NSEG-1)), 128, S2_SMEM>>>(A_log, l);
    // GEMM4 fused pairs: o[p] = [u(2p) u(2p+1)] @ stacked Wt (K=1024)
    hgemm_pair_ker<<<dim3(MM/128, 2, 2), 256, SMEM_H128>>>(l);
    combine_ker<<<MM, 256>>>(ln_w, ln_b, (float*)d_out, (l == NLAY-1) ? 1 : 0);
  }
}

// round 16
// speedup vs baseline: 1.0537x; 1.0345x over previous
#include <cuda_runtime.h>
#include <cuda_fp16.h>
#include <math.h>
#include <stdint.h>

// Problem dims
#define Bb   8
#define Oo   12
#define Tt   64
#define DMF  256
#define DIF  512
#define DSF  16
#define LL   768          // Oo*Tt
#define MM   6144         // Bb*LL
#define NLAY 2
#define NSEG 8
#define LSEG 96           // LL/NSEG

// ---------------- scratch (static device globals; no runtime allocs) -------
__device__ float  g_x   [MM*DMF];                     // fp32 residual stream
__device__ __align__(16) __half g_xh  [MM*DMF];       // half residual copy
__device__ __align__(16) __half g_xzh [4][(size_t)MM*2*DIF]; // GEMM1 out (half)
__device__ __align__(16) __half g_xch [4][(size_t)MM*DIF];   // conv out (half)
__device__ float  g_dbl [4][(size_t)MM*48];           // GEMM2 out
__device__ __align__(16) __half g_uh  [4][(size_t)MM*DIF];   // scan out (half)
__device__ __align__(8)  __half2 g_dg [4][(size_t)MM*DIF];   // (dv, gate) per step
__device__ float  g_hf  [4*8*NSEG*DIF*16];            // per-segment final h
__device__ float  g_sdv [4*8*NSEG*DIF];               // per-segment sum(dv)
__device__ float  g_o   [4][(size_t)MM*DMF];          // GEMM4 out
// transposed + half weights: [w][n][k]
__device__ __align__(16) __half g_wt1[8*1024*256];
__device__ __align__(16) __half g_wt2[8*64*512];
__device__ __align__(16) __half g_wt4[8*256*512];

__device__ __forceinline__ float siluf(float x){ return x / (1.f + __expf(-x)); }

// ---------------- PTX helpers ----------------------------------------------
__device__ __forceinline__ void mma_f16(float* c, const uint32_t* a, const uint32_t* b){
  asm volatile(
    "mma.sync.aligned.m16n8k16.row.col.f32.f16.f16.f32 "
    "{%0,%1,%2,%3}, {%4,%5,%6,%7}, {%8,%9}, {%0,%1,%2,%3};\n"
    : "+f"(c[0]), "+f"(c[1]), "+f"(c[2]), "+f"(c[3])
    : "r"(a[0]), "r"(a[1]), "r"(a[2]), "r"(a[3]), "r"(b[0]), "r"(b[1]));
}
__device__ __forceinline__ void ldsm4(uint32_t* r, uint32_t addr){
  asm volatile("ldmatrix.sync.aligned.m8n8.x4.shared.b16 {%0,%1,%2,%3}, [%4];"
    : "=r"(r[0]), "=r"(r[1]), "=r"(r[2]), "=r"(r[3]) : "r"(addr));
}
__device__ __forceinline__ void cpa16(uint32_t dst, const void* src){
  asm volatile("cp.async.cg.shared.global [%0], [%1], 16;" :: "r"(dst), "l"(src));
}

// ---------------- weight transpose + fp16 convert ---------------------------
__global__ void wtrans_ker(const float* __restrict__ ip, const float* __restrict__ xp,
                           const float* __restrict__ op){
  int s = blockIdx.z >> 3;
  int w = blockIdx.z & 7;
  int K = (s==0)?256:512;
  int N = (s==0)?1024:((s==1)?48:256);
  int Nout = (s==1)?64:N;
  const float* src = (s==0)?ip:((s==1)?xp:op);
  __half* dst = (s==0)?g_wt1:((s==1)?g_wt2:g_wt4);
  src += (size_t)w*K*N; dst += (size_t)w*(size_t)Nout*K;
  int k0 = blockIdx.x*32, n0 = blockIdx.y*32;
  if (k0 >= K || n0 >= Nout) return;
  __shared__ float tile[32][33];
  int tx = threadIdx.x, ty = threadIdx.y;
  for (int i = ty; i < 32; i += 8){
    int k = k0+i, n = n0+tx;
    tile[i][tx] = (k < K && n < N) ? src[(size_t)k*N + n] : 0.f;
  }
  __syncthreads();
  for (int i = ty; i < 32; i += 8){
    int n = n0+i, k = k0+tx;
    if (n < Nout && k < K) dst[(size_t)n*K + k] = __float2half(tile[tx][i]);
  }
}

// ---------------- elementwise kernels --------------------------------------
__global__ void add_pe_ker(const float* __restrict__ x, const float* __restrict__ pe){
  int i = blockIdx.x, c = threadIdx.x;
  int t = i % Tt;
  float v = x[(size_t)i*DMF + c] + pe[t*DMF + c];
  g_x [(size_t)i*DMF + c] = v;
  g_xh[(size_t)i*DMF + c] = __float2half(v);
}

// ---------------- fp16 tensor-core GEMM (ldmatrix + cp.async) --------------
#define STRH 40
#define ABUF (128*STRH)
template<int NT>
__global__ void __launch_bounds__(256) hgemm_ker(
    const __half* __restrict__ A0, size_t zstr,
    const __half* __restrict__ WtB, void* __restrict__ Cb,
    int K, int Ntot, int l, int perm, int hout)
{
  constexpr int BBUF = NT*STRH;
  extern __shared__ __half smh[];
  const uint32_t sb = (uint32_t)__cvta_generic_to_shared(smh);
  const uint32_t aOff[2] = {0u, (uint32_t)ABUF*2u};
  const uint32_t bOff[2] = {(uint32_t)(2*ABUF)*2u, (uint32_t)(2*ABUF + BBUF)*2u};

  const int z = blockIdx.z;
  const __half* A = A0 + (size_t)z*zstr;
  const int n0 = blockIdx.y * NT;
  const int Nrows = (Ntot==48) ? 64 : Ntot;
  const __half* Wt = WtB + ((size_t)(l*4 + z)*Nrows + n0) * K;

  const int tid  = threadIdx.x;
  const int lane = tid & 31;
  const int w    = tid >> 5;
  constexpr int WN = NT/4;
  constexpr int NATOMS = WN/8;
  constexpr int NPAIRS = WN/16;
  const int wm = (w & 1) * 64;
  const int wn = (w >> 1) * WN;
  const int row0 = blockIdx.x * 128;

  float acc[4][NATOMS][4];
  #pragma unroll
  for (int ma = 0; ma < 4; ma++)
    #pragma unroll
    for (int na = 0; na < NATOMS; na++)
      #pragma unroll
      for (int q = 0; q < 4; q++) acc[ma][na][q] = 0.f;

  const int a_r = tid >> 1;
  const int a_u = (tid & 1) * 2;
  int grow = row0 + a_r;
  if (perm && z >= 2){
    int b2 = grow / LL;
    int p  = grow - b2*LL;
    int tq = p / Oo;
    int o  = p - tq*Oo;
    grow = b2*LL + o*Tt + tq;
  }
  const __half* Arow = A + (size_t)grow*K;

  const uint32_t aLd = (uint32_t)((wm + (lane & 15))*STRH + (lane >> 4)*8) * 2u;
  const int nloc = ((lane & 16) >> 1) | (lane & 7);
  const uint32_t bLd = (uint32_t)((wn + nloc)*STRH + ((lane >> 3) & 1)*8) * 2u;

  auto load_chunk = [&](int buf, int c){
    const int kb = c*32;
    const uint32_t ab = sb + aOff[buf];
    const uint32_t bb = sb + bOff[buf];
    #pragma unroll
    for (int u = 0; u < 2; u++)
      cpa16(ab + (uint32_t)(a_r*STRH + (a_u+u)*8)*2u, Arow + kb + (a_u+u)*8);
    #pragma unroll
    for (int it = 0; it < NT/64; it++){
      int idx = tid + it*256;
      int r = idx >> 2, u = idx & 3;
      cpa16(bb + (uint32_t)(r*STRH + u*8)*2u, &Wt[(size_t)r*K + kb + u*8]);
    }
    asm volatile("cp.async.commit_group;" ::: "memory");
  };

  auto compute = [&](int buf){
    const uint32_t ab = sb + aOff[buf];
    const uint32_t bb = sb + bOff[buf];
    #pragma unroll
    for (int ks = 0; ks < 2; ks++){
      uint32_t af[4][4];
      #pragma unroll
      for (int ma = 0; ma < 4; ma++)
        ldsm4(af[ma], ab + aLd + (uint32_t)(ma*16*STRH + ks*16)*2u);
      uint32_t bf[2*NPAIRS][2];
      #pragma unroll
      for (int np = 0; np < NPAIRS; np++){
        uint32_t r4[4];
        ldsm4(r4, bb + bLd + (uint32_t)(np*16*STRH + ks*16)*2u);
        bf[np*2+0][0] = r4[0]; bf[np*2+0][1] = r4[1];
        bf[np*2+1][0] = r4[2]; bf[np*2+1][1] = r4[3];
      }
      #pragma unroll
      for (int ma = 0; ma < 4; ma++)
        #pragma unroll
        for (int na = 0; na < NATOMS; na++)
          mma_f16(acc[ma][na], af[ma], bf[na]);
    }
  };

  const int nc = K / 32;
  load_chunk(0, 0);
  for (int c = 0; c < nc; c++){
    const int buf = c & 1;
    if (c + 1 < nc){
      load_chunk(buf ^ 1, c + 1);
      asm volatile("cp.async.wait_group 1;" ::: "memory");
    } else {
      asm volatile("cp.async.wait_group 0;" ::: "memory");
    }
    __syncthreads();
    compute(buf);
    __syncthreads();
  }

  if (hout){
    __half* Ch = (__half*)Cb + (size_t)z * (size_t)MM * Ntot;
    #pragma unroll
    for (int ma = 0; ma < 4; ma++){
      const int r = row0 + wm + ma*16 + (lane >> 2);
      #pragma unroll
      for (int na = 0; na < NATOMS; na++){
        const int cc = n0 + wn + na*8 + (lane & 3)*2;
        if (cc < Ntot){
          *reinterpret_cast<__half2*>(&Ch[(size_t)r*Ntot + cc])     = __floats2half2_rn(acc[ma][na][0], acc[ma][na][1]);
          *reinterpret_cast<__half2*>(&Ch[(size_t)(r+8)*Ntot + cc]) = __floats2half2_rn(acc[ma][na][2], acc[ma][na][3]);
        }
      }
    }
  } else {
    float* C = (float*)Cb + (size_t)z * (size_t)MM * Ntot;
    #pragma unroll
    for (int ma = 0; ma < 4; ma++){
      const int r = row0 + wm + ma*16 + (lane >> 2);
      #pragma unroll
      for (int na = 0; na < NATOMS; na++){
        const int cc = n0 + wn + na*8 + (lane & 3)*2;
        if (cc < Ntot){
          *reinterpret_cast<float2*>(&C[(size_t)r*Ntot + cc])     = make_float2(acc[ma][na][0], acc[ma][na][1]);
          *reinterpret_cast<float2*>(&C[(size_t)(r+8)*Ntot + cc]) = make_float2(acc[ma][na][2], acc[ma][na][3]);
        }
      }
    }
  }
}

// ---------------- depthwise causal conv + SiLU (half in/out, 4 t/thread) ---
__global__ void conv_ker(const float* __restrict__ conv_w, const float* __restrict__ conv_b, int l){
  int z   = blockIdx.y;
  int gid = blockIdx.x*256 + threadIdx.x;
  const int NT4 = LL/4;
  int i4 = gid / (DIF/4);
  int dq = gid % (DIF/4);
  int d  = dq*4;
  int b  = i4 / NT4;
  int t0 = (i4 - b*NT4)*4;
  int widx = l*4 + z;
  const __half* xz = g_xzh[z];

  float wv[4][4], bi[4];
  #pragma unroll
  for (int di = 0; di < 4; di++){
    float4 w4 = *reinterpret_cast<const float4*>(&conv_w[(size_t)(widx*DIF + d+di)*4]);
    wv[di][0]=w4.x; wv[di][1]=w4.y; wv[di][2]=w4.z; wv[di][3]=w4.w;
  }
  {
    float4 b4 = *reinterpret_cast<const float4*>(&conv_b[(size_t)widx*DIF + d]);
    bi[0]=b4.x; bi[1]=b4.y; bi[2]=b4.z; bi[3]=b4.w;
  }
  size_t base = (size_t)b*LL;
  float v[7][4];
  bool fwd = ((z & 1) == 0);
  #pragma unroll
  for (int j = 0; j < 7; j++){
    int tt = fwd ? (t0 + j - 3) : (t0 + j);
    if (tt >= 0 && tt < LL){
      const __half2* p2 = reinterpret_cast<const __half2*>(&xz[(base+tt)*1024 + d]);
      float2 a = __half22float2(p2[0]), c2 = __half22float2(p2[1]);
      v[j][0]=a.x; v[j][1]=a.y; v[j][2]=c2.x; v[j][3]=c2.y;
    } else {
      v[j][0]=v[j][1]=v[j][2]=v[j][3]=0.f;
    }
  }
  #pragma unroll
  for (int k = 0; k < 4; k++){
    float o[4];
    #pragma unroll
    for (int di = 0; di < 4; di++){
      float s = bi[di];
      if (fwd){
        #pragma unroll
        for (int i2 = 0; i2 < 4; i2++) s = fmaf(wv[di][i2], v[k+i2][di], s);
      } else {
        #pragma unroll
        for (int j = 0; j < 4; j++)    s = fmaf(wv[di][3-j], v[k+j][di], s);
      }
      o[di] = siluf(s);
    }
    __half2* oh = reinterpret_cast<__half2*>(&g_xch[z][(base + t0 + k)*DIF + d]);
    oh[0] = __floats2half2_rn(o[0], o[1]);
    oh[1] = __floats2half2_rn(o[2], o[3]);
  }
}

// ---------------- scan phase 1: per-segment local scan (h0 = 0) ------------
#define S1CH 32
#define oDBL 0
#define oXC  12288
#define oZ   28672
#define S1_SMEM 45056
__global__ void __launch_bounds__(128) scan1_ker(const float* __restrict__ A_log,
                                                 const float* __restrict__ Dp,
                                                 const float* __restrict__ dtw,
                                                 const float* __restrict__ dtb, int l){
  extern __shared__ char ssm[];
  const uint32_t sb = (uint32_t)__cvta_generic_to_shared(ssm);
  int tid = threadIdx.x;
  int d0 = blockIdx.x*128, d = d0 + tid;
  int b = blockIdx.y;
  int z = blockIdx.z >> 3, seg = blockIdx.z & 7;
  int widx = l*4 + z;
  bool bwd = (z & 1);
  const __half* xch = g_xch[z];
  const __half* xzz = g_xzh[z];
  const float*  dbl = g_dbl[z];
  __half*  u  = g_uh[z];
  __half2* dg = g_dg[z];

  float W[16];
  #pragma unroll
  for (int k = 0; k < 16; k++) W[k] = dtw[((size_t)widx*16 + k)*DIF + d];
  float bia = dtb[(size_t)widx*DIF + d];
  float Av[16];
  #pragma unroll
  for (int s = 0; s < 16; s++)
    Av[s] = -expf(A_log[((size_t)widx*DIF + d)*DSF + s]);
  bool pc = true;
  #pragma unroll
  for (int s = 1; s < 16; s++)
    pc = pc && (fabsf(Av[s] - (float)(s+1)*Av[0]) <= 1e-4f * fabsf(Av[s]));
  float Dpar = Dp[(size_t)widx*DIF + d];

  float h[16];
  #pragma unroll
  for (int s = 0; s < 16; s++) h[s] = 0.f;
  float sumdv = 0.f;
  const int gi0 = seg*LSEG;

  auto load_chunk = [&](int c, int buf){
    #pragma unroll
    for (int it = 0; it < 3; it++){
      int idx = tid + it*128;
      int ls = idx / 12, q = idx - ls*12;
      int gi = gi0 + c*S1CH + ls;
      int t = bwd ? (LL-1 - gi) : gi;
      cpa16(sb + oDBL + (uint32_t)(((buf*S1CH + ls)*12 + q)*16),
            &dbl[(size_t)(b*LL + t)*48 + q*4]);
    }
    #pragma unroll
    for (int it = 0; it < 4; it++){
      int idx = tid + it*128;
      int ls = idx >> 4, sg = idx & 15;
      int gi = gi0 + c*S1CH + ls;
      int t = bwd ? (LL-1 - gi) : gi;
      cpa16(sb + oXC + (uint32_t)(((buf*S1CH + ls)*128 + sg*8)*2),
            &xch[(size_t)(b*LL + t)*DIF + d0 + sg*8]);
      cpa16(sb + oZ + (uint32_t)(((buf*S1CH + ls)*128 + sg*8)*2),
            &xzz[(size_t)(b*LL + t)*1024 + DIF + d0 + sg*8]);
    }
    asm volatile("cp.async.commit_group;" ::: "memory");
  };

  const int nc = LSEG / S1CH;   // 3
  load_chunk(0, 0);
  for (int c = 0; c < nc; c++){
    const int buf = c & 1;
    if (c + 1 < nc){
      load_chunk(c + 1, buf ^ 1);
      asm volatile("cp.async.wait_group 1;" ::: "memory");
    } else {
      asm volatile("cp.async.wait_group 0;" ::: "memory");
    }
    __syncthreads();
    const float4* sD = reinterpret_cast<const float4*>(ssm + oDBL) + (size_t)buf*S1CH*12;
    const __half* sX = reinterpret_cast<const __half*>(ssm + oXC) + (size_t)buf*S1CH*128;
    const __half* sZ = reinterpret_cast<const __half*>(ssm + oZ)  + (size_t)buf*S1CH*128;

    for (int ls = 0; ls < S1CH; ls++){
      int gi = gi0 + c*S1CH + ls;
      int t  = bwd ? (LL-1 - gi) : gi;
      float xcv = __half2float(sX[ls*128 + tid]);
      float zv  = __half2float(sZ[ls*128 + tid]);
      const float4* row = sD + ls*12;
      float4 q0 = row[0], q1 = row[1], q2 = row[2], q3 = row[3];
      float a0 = fmaf(q0.x, W[0],  fmaf(q0.y, W[1],  fmaf(q0.z, W[2],  q0.w*W[3])));
      float a1 = fmaf(q1.x, W[4],  fmaf(q1.y, W[5],  fmaf(q1.z, W[6],  q1.w*W[7])));
      float a2 = fmaf(q2.x, W[8],  fmaf(q2.y, W[9],  fmaf(q2.z, W[10], q2.w*W[11])));
      float a3 = fmaf(q3.x, W[12], fmaf(q3.y, W[13], fmaf(q3.z, W[14], q3.w*W[15])));
      float a = bia + ((a0 + a1) + (a2 + a3));
      float dv = fmaxf(a, 0.f) + log1pf(__expf(-fabsf(a)));
      sumdv += dv;
      float du = dv * xcv;

      float acc0 = 0.f, acc1 = 0.f, acc2 = 0.f, acc3 = 0.f;
      if (pc){
        float e1 = __expf(dv * Av[0]);
        float e2 = e1*e1, e3 = e2*e1, e4 = e2*e2;
        float e5 = e4*e1, e6 = e4*e2, e7 = e4*e3, e8 = e4*e4;
        float e9 = e8*e1, e10 = e8*e2, e11 = e8*e3, e12 = e8*e4;
        float e13 = e8*e5, e14 = e8*e6, e15 = e8*e7, e16 = e8*e8;
        float4 B0 = row[4], B1 = row[5], B2 = row[6], B3 = row[7];
        float4 C0 = row[8], C1 = row[9], C2 = row[10], C3 = row[11];
        h[0]  = fmaf(e1,  h[0],  du*B0.x); acc0 = fmaf(h[0],  C0.x, acc0);
        h[1]  = fmaf(e2,  h[1],  du*B0.y); acc1 = fmaf(h[1],  C0.y, acc1);
        h[2]  = fmaf(e3,  h[2],  du*B0.z); acc2 = fmaf(h[2],  C0.z, acc2);
        h[3]  = fmaf(e4,  h[3],  du*B0.w); acc3 = fmaf(h[3],  C0.w, acc3);
        h[4]  = fmaf(e5,  h[4],  du*B1.x); acc0 = fmaf(h[4],  C1.x, acc0);
        h[5]  = fmaf(e6,  h[5],  du*B1.y); acc1 = fmaf(h[5],  C1.y, acc1);
        h[6]  = fmaf(e7,  h[6],  du*B1.z); acc2 = fmaf(h[6],  C1.z, acc2);
        h[7]  = fmaf(e8,  h[7],  du*B1.w); acc3 = fmaf(h[7],  C1.w, acc3);
        h[8]  = fmaf(e9,  h[8],  du*B2.x); acc0 = fmaf(h[8],  C2.x, acc0);
        h[9]  = fmaf(e10, h[9],  du*B2.y); acc1 = fmaf(h[9],  C2.y, acc1);
        h[10] = fmaf(e11, h[10], du*B2.z); acc2 = fmaf(h[10], C2.z, acc2);
        h[11] = fmaf(e12, h[11], du*B2.w); acc3 = fmaf(h[11], C2.w, acc3);
        h[12] = fmaf(e13, h[12], du*B3.x); acc0 = fmaf(h[12], C3.x, acc0);
        h[13] = fmaf(e14, h[13], du*B3.y); acc1 = fmaf(h[13], C3.y, acc1);
        h[14] = fmaf(e15, h[14], du*B3.z); acc2 = fmaf(h[14], C3.z, acc2);
        h[15] = fmaf(e16, h[15], du*B3.w); acc3 = fmaf(h[15], C3.w, acc3);
      } else {
        #pragma unroll
        for (int q = 0; q < 4; q++){
          float4 B4 = row[4+q];
          float4 C4 = row[8+q];
          float b0 = __expf(dv*Av[q*4+0]); h[q*4+0] = fmaf(b0, h[q*4+0], du*B4.x); acc0 = fmaf(h[q*4+0], C4.x, acc0);
          float b1 = __expf(dv*Av[q*4+1]); h[q*4+1] = fmaf(b1, h[q*4+1], du*B4.y); acc1 = fmaf(h[q*4+1], C4.y, acc1);
          float b2 = __expf(dv*Av[q*4+2]); h[q*4+2] = fmaf(b2, h[q*4+2], du*B4.z); acc2 = fmaf(h[q*4+2], C4.z, acc2);
          float b3 = __expf(dv*Av[q*4+3]); h[q*4+3] = fmaf(b3, h[q*4+3], du*B4.w); acc3 = fmaf(h[q*4+3], C4.w, acc3);
        }
      }
      float gate = siluf(zv);
      float y = (acc0 + acc1) + (acc2 + acc3) + xcv * Dpar;
      size_t rowd = (size_t)(b*LL + t)*DIF + d;
      u[rowd]  = __float2half(y * gate);
      dg[rowd] = __floats2half2_rn(dv, gate);
    }
    __syncthreads();
  }
  int segbase = ((z*8 + b)*NSEG + seg)*DIF + d;
  float4* hf4 = reinterpret_cast<float4*>(&g_hf[(size_t)segbase*16]);
  hf4[0] = make_float4(h[0],  h[1],  h[2],  h[3]);
  hf4[1] = make_float4(h[4],  h[5],  h[6],  h[7]);
  hf4[2] = make_float4(h[8],  h[9],  h[10], h[11]);
  hf4[3] = make_float4(h[12], h[13], h[14], h[15]);
  g_sdv[segbase] = sumdv;
}

// ---------------- scan phase 2: cross-segment correction (early exit) ------
#define S2CH 32
#define oC2  0
#define oDG2 4096
#define oU2  36864
#define S2_SMEM 53248
__global__ void __launch_bounds__(128) scan2_ker(const float* __restrict__ A_log, int l){
  extern __shared__ char ssm[];
  const uint32_t sb = (uint32_t)__cvta_generic_to_shared(ssm);
  int tid = threadIdx.x;
  int d0 = blockIdx.x*128, d = d0 + tid;
  int b = blockIdx.y;
  int z = blockIdx.z / (NSEG-1), seg = blockIdx.z - z*(NSEG-1) + 1;
  int widx = l*4 + z;
  bool bwd = (z & 1);
  const float*  dbl = g_dbl[z];
  const __half2* dg = g_dg[z];
  __half* u = g_uh[z];

  float Av[16];
  #pragma unroll
  for (int s = 0; s < 16; s++)
    Av[s] = -expf(A_log[((size_t)widx*DIF + d)*DSF + s]);
  bool pc = true;
  #pragma unroll
  for (int s = 1; s < 16; s++)
    pc = pc && (fabsf(Av[s] - (float)(s+1)*Av[0]) <= 1e-4f * fabsf(Av[s]));
  float amax = Av[0];
  #pragma unroll
  for (int s = 1; s < 16; s++) amax = fmaxf(amax, Av[s]);

  float hin[16];
  #pragma unroll
  for (int s = 0; s < 16; s++) hin[s] = 0.f;
  for (int k = 0; k < seg; k++){
    int kb = ((z*8 + b)*NSEG + k)*DIF + d;
    float sd = g_sdv[kb];
    const float4* hf4 = reinterpret_cast<const float4*>(&g_hf[(size_t)kb*16]);
    float4 f0 = hf4[0], f1 = hf4[1], f2 = hf4[2], f3 = hf4[3];
    float hf[16] = {f0.x,f0.y,f0.z,f0.w, f1.x,f1.y,f1.z,f1.w,
                    f2.x,f2.y,f2.z,f2.w, f3.x,f3.y,f3.z,f3.w};
    if (pc){
      float E = __expf(Av[0]*sd);
      float p = 1.f;
      #pragma unroll
      for (int s = 0; s < 16; s++){ p *= E; hin[s] = fmaf(p, hin[s], hf[s]); }
    } else {
      #pragma unroll
      for (int s = 0; s < 16; s++) hin[s] = fmaf(__expf(Av[s]*sd), hin[s], hf[s]);
    }
  }

  const int gi0 = seg*LSEG;
  auto load_chunk = [&](int c, int buf){
    {
      int ls = tid >> 2, q = tid & 3;
      int gi = gi0 + c*S2CH + ls;
      int t = bwd ? (LL-1 - gi) : gi;
      cpa16(sb + oC2 + (uint32_t)(((buf*S2CH + ls)*4 + q)*16),
            &dbl[(size_t)(b*LL + t)*48 + 32 + q*4]);
    }
    #pragma unroll
    for (int it = 0; it < 8; it++){
      int idx = tid + it*128;
      int ls = idx >> 5, sg = idx & 31;
      int gi = gi0 + c*S2CH + ls;
      int t = bwd ? (LL-1 - gi) : gi;
      cpa16(sb + oDG2 + (uint32_t)(((buf*S2CH + ls)*128 + sg*4)*4),
            &dg[(size_t)(b*LL + t)*DIF + d0 + sg*4]);
    }
    #pragma unroll
    for (int it = 0; it < 4; it++){
      int idx = tid + it*128;
      int ls = idx >> 4, sg = idx & 15;
      int gi = gi0 + c*S2CH + ls;
      int t = bwd ? (LL-1 - gi) : gi;
      cpa16(sb + oU2 + (uint32_t)(((buf*S2CH + ls)*128 + sg*8)*2),
            &u[(size_t)(b*LL + t)*DIF + d0 + sg*8]);
    }
    asm volatile("cp.async.commit_group;" ::: "memory");
  };

  float cacc = 0.f;
  const int nc = LSEG / S2CH;   // 3
  load_chunk(0, 0);
  for (int c = 0; c < nc; c++){
    const int buf = c & 1;
    if (c + 1 < nc){
      load_chunk(c + 1, buf ^ 1);
      asm volatile("cp.async.wait_group 1;" ::: "memory");
    } else {
      asm volatile("cp.async.wait_group 0;" ::: "memory");
    }
    __syncthreads();
    const float4*  sC = reinterpret_cast<const float4*>(ssm + oC2) + (size_t)buf*S2CH*4;
    const __half2* sG = reinterpret_cast<const __half2*>(ssm + oDG2) + (size_t)buf*S2CH*128;
    const __half*  sU = reinterpret_cast<const __half*>(ssm + oU2) + (size_t)buf*S2CH*128;

    for (int ls = 0; ls < S2CH; ls++){
      int gi = gi0 + c*S2CH + ls;
      int t  = bwd ? (LL-1 - gi) : gi;
      float2 dgv = __half22float2(sG[ls*128 + tid]);
      cacc += dgv.x;
      float4 C0 = sC[ls*4+0], C1 = sC[ls*4+1], C2 = sC[ls*4+2], C3 = sC[ls*4+3];
      float corr;
      if (pc){
        float e1 = __expf(Av[0]*cacc);
        float e2 = e1*e1, e3 = e2*e1, e4 = e2*e2;
        float e5 = e4*e1, e6 = e4*e2, e7 = e4*e3, e8 = e4*e4;
        float e9 = e8*e1, e10 = e8*e2, e11 = e8*e3, e12 = e8*e4;
        float e13 = e8*e5, e14 = e8*e6, e15 = e8*e7, e16 = e8*e8;
        float c0 = fmaf(e1*hin[0],  C0.x, 0.f);
        c0 = fmaf(e5*hin[4],  C1.x, c0);
        c0 = fmaf(e9*hin[8],  C2.x, c0);
        c0 = fmaf(e13*hin[12], C3.x, c0);
        float c1 = fmaf(e2*hin[1],  C0.y, 0.f);
        c1 = fmaf(e6*hin[5],  C1.y, c1);
        c1 = fmaf(e10*hin[9], C2.y, c1);
        c1 = fmaf(e14*hin[13], C3.y, c1);
        float c2 = fmaf(e3*hin[2],  C0.z, 0.f);
        c2 = fmaf(e7*hin[6],  C1.z, c2);
        c2 = fmaf(e11*hin[10], C2.z, c2);
        c2 = fmaf(e15*hin[14], C3.z, c2);
        float c3 = fmaf(e4*hin[3],  C0.w, 0.f);
        c3 = fmaf(e8*hin[7],  C1.w, c3);
        c3 = fmaf(e12*hin[11], C2.w, c3);
        c3 = fmaf(e16*hin[15], C3.w, c3);
        corr = (c0 + c1) + (c2 + c3);
      } else {
        float Cw[16] = {C0.x,C0.y,C0.z,C0.w, C1.x,C1.y,C1.z,C1.w,
                        C2.x,C2.y,C2.z,C2.w, C3.x,C3.y,C3.z,C3.w};
        corr = 0.f;
        #pragma unroll
        for (int s = 0; s < 16; s++)
          corr = fmaf(__expf(Av[s]*cacc)*hin[s], Cw[s], corr);
      }
      float up = __half2float(sU[ls*128 + tid]);
      u[(size_t)(b*LL + t)*DIF + d] = __float2half(fmaf(corr, dgv.y, up));
    }
    int done = (cacc * (-amax) > 25.f) ? 1 : 0;
    if (__syncthreads_and(done)){
      asm volatile("cp.async.wait_group 0;" ::: "memory");
      break;
    }
  }
}

// ---------------- combine: LN(o0+o1), LN(o2+o3), residual; warp-shfl -------
__device__ __forceinline__ float blk_sum(float v, float* sw, int tid){
  #pragma unroll
  for (int o = 16; o > 0; o >>= 1) v += __shfl_down_sync(0xffffffffu, v, o);
  if ((tid & 31) == 0) sw[tid >> 5] = v;
  __syncthreads();
  float r = (tid < 8) ? sw[tid] : 0.f;
  #pragma unroll
  for (int o = 4; o > 0; o >>= 1) r += __shfl_down_sync(0xffu, r, o);
  if (tid == 0) sw[0] = r;
  __syncthreads();
  float out = sw[0];
  __syncthreads();
  return out;
}

__global__ void combine_ker(const float* __restrict__ lnw, const float* __restrict__ lnb,
                            float* __restrict__ out, int last){
  int i = blockIdx.x, c = threadIdx.x;
  float a  = g_o[0][(size_t)i*DMF + c] + g_o[1][(size_t)i*DMF + c];
  float bv = g_o[2][(size_t)i*DMF + c] + g_o[3][(size_t)i*DMF + c];
  __shared__ float sw[8];
  float ma = blk_sum(a,  sw, c) * (1.f/DMF);
  float mb = blk_sum(bv, sw, c) * (1.f/DMF);
  float da = a - ma, db = bv - mb;
  float va = blk_sum(da*da, sw, c) * (1.f/DMF);
  float vb = blk_sum(db*db, sw, c) * (1.f/DMF);
  float s1 = da * rsqrtf(va + 1e-5f) * lnw[c] + lnb[c];
  float s2 = db * rsqrtf(vb + 1e-5f) * lnw[c] + lnb[c];
  float nv = g_x[(size_t)i*DMF + c] + 0.5f * (s1 + s2);
  g_x [(size_t)i*DMF + c] = nv;
  g_xh[(size_t)i*DMF + c] = __float2half(nv);
  if (last) out[(size_t)i*DMF + c] = nv;
}

// ---------------- host orchestration ---------------------------------------
#define SMEM_H128 ((2*ABUF + 2*128*STRH)*2)   // 40960 B
#define SMEM_H64  ((2*ABUF + 2*64*STRH)*2)    // 30720 B

extern "C" void kernel_launch(void* const* d_in, const int* in_sizes, int n_in,
                              void* d_out, int out_size){
  const float* x       = (const float*)d_in[0];
  const float* pe      = (const float*)d_in[1];
  const float* ln_w    = (const float*)d_in[2];
  const float* ln_b    = (const float*)d_in[3];
  const float* in_proj = (const float*)d_in[4];
  const float* conv_w  = (const float*)d_in[5];
  const float* conv_b  = (const float*)d_in[6];
  const float* x_proj  = (const float*)d_in[7];
  const float* dt_w    = (const float*)d_in[8];
  const float* dt_b    = (const float*)d_in[9];
  const float* A_log   = (const float*)d_in[10];
  const float* Dp      = (const float*)d_in[11];
  const float* out_prj = (const float*)d_in[12];

  void *pxh, *pxzh, *pxch, *pdbl, *puh, *po, *pw1, *pw2, *pw4;
  cudaGetSymbolAddress(&pxh,  g_xh);
  cudaGetSymbolAddress(&pxzh, g_xzh);
  cudaGetSymbolAddress(&pxch, g_xch);
  cudaGetSymbolAddress(&pdbl, g_dbl);
  cudaGetSymbolAddress(&puh,  g_uh);
  cudaGetSymbolAddress(&po,   g_o);
  cudaGetSymbolAddress(&pw1,  g_wt1);
  cudaGetSymbolAddress(&pw2,  g_wt2);
  cudaGetSymbolAddress(&pw4,  g_wt4);

  cudaFuncSetAttribute(scan1_ker, cudaFuncAttributeMaxDynamicSharedMemorySize, S1_SMEM);
  cudaFuncSetAttribute(scan2_ker, cudaFuncAttributeMaxDynamicSharedMemorySize, S2_SMEM);

  wtrans_ker<<<dim3(16, 32, 24), dim3(32, 8)>>>(in_proj, x_proj, out_prj);
  add_pe_ker<<<MM, 256>>>(x, pe);

  for (int l = 0; l < NLAY; l++){
    // GEMM1: xz[z] = seq(z) @ in_proj[l,z]  (N=1024, K=256, half out)
    hgemm_ker<128><<<dim3(MM/128, 8, 4), 256, SMEM_H128>>>(
        (const __half*)pxh, (size_t)0,
        (const __half*)pw1, pxzh, 256, 1024, l, 1, 1);
    conv_ker<<<dim3((MM/4)*(DIF/4)/256, 4), 256>>>(conv_w, conv_b, l);
    // GEMM2: dbl[z] = xc[z] @ x_proj (N=48 pad 64, K=512, fp32 out)
    hgemm_ker<64><<<dim3(MM/128, 1, 4), 256, SMEM_H64>>>(
        (const __half*)pxch, (size_t)MM*DIF,
        (const __half*)pw2, pdbl, 512, 48, l, 0, 0);
    // selective scan: 8-segment phase 1 (chunk 32) + early-exit fixup
    scan1_ker<<<dim3(4, Bb, 4*NSEG), 128, S1_SMEM>>>(A_log, Dp, dt_w, dt_b, l);
    scan2_ker<<<dim3(4, Bb, 4*(NSEG-1)), 128, S2_SMEM>>>(A_log, l);
    // GEMM4: o[z] = u[z] @ out_proj (N=256, K=512, fp32 out) — 384 blocks
    hgemm_ker<128><<<dim3(MM/128, 2, 4), 256, SMEM_H128>>>(
        (const __half*)puh, (size_t)MM*DIF,
        (const __half*)pw4, po, 512, 256, l, 0, 0);
    combine_ker<<<MM, 256>>>(ln_w, ln_b, (float*)d_out, (l == NLAY-1) ? 1 : 0);
  }
}